// round 1
// baseline (speedup 1.0000x reference)
#include <cuda_runtime.h>
#include <cstddef>

#define B   32
#define S   512
#define E   300
#define H   200
#define G3  600          // 3*H gate rows
#define LBL 10
#define ROWS (B*S)       // 16384

#define CKK   44         // cached kk per k-half
#define CROWS (2*CKK)    // 88 cached k-rows of w_hh^T

// ---------------- scratch (device globals: no allocations allowed) ----------
__device__ float g_gi [2u*ROWS*(size_t)G3];   // [dir][b*S+s][g]  ~78.6 MB
__device__ float g_wt [2*H*G3];               // w_hh transposed: [dir][k][g]
__device__ float g_hid[2u*ROWS*(size_t)H];    // hidden outputs   ~26.2 MB

// ---------------- prep: transpose w_hh into [k][g] ----------
__global__ void prep_transpose(const float* __restrict__ wf,
                               const float* __restrict__ wb) {
    int i = blockIdx.x * blockDim.x + threadIdx.x;
    if (i < G3 * H) {
        int g = i / H, k = i - g * H;
        g_wt[k * G3 + g]          = wf[i];
        g_wt[H * G3 + k * G3 + g] = wb[i];
    }
}

// ---------------- gi = emb[text] @ w_ih^T + b_ih (both dirs) ----------
__global__ void gi_gemm(const int*   __restrict__ text,
                        const float* __restrict__ emb,
                        const float* __restrict__ wih_f,
                        const float* __restrict__ bih_f,
                        const float* __restrict__ wih_b,
                        const float* __restrict__ bih_b) {
    const int d = blockIdx.z;
    const float* wih = d ? wih_b : wih_f;
    const float* bih = d ? bih_b : bih_f;

    __shared__ float As[16][65];   // [k][m], padded for conflict-free stores
    __shared__ float Bs[16][65];   // [k][n]
    __shared__ int   tok[64];

    const int tid = threadIdx.x;
    const int by = blockIdx.y, gx = blockIdx.x;

    if (tid < 64) tok[tid] = text[by * 64 + tid];
    __syncthreads();

    const int lk = tid & 15;   // k within tile
    const int lm = tid >> 4;   // base row
    const int ty = tid >> 4, tx = tid & 15;

    float c[4][4] = {};

    for (int k0 = 0; k0 < E; k0 += 16) {
        #pragma unroll
        for (int p = 0; p < 4; ++p) {
            int m  = lm + p * 16;
            int kk = k0 + lk;
            As[lk][m] = (kk < E) ? emb[(size_t)tok[m] * E + kk] : 0.f;
            int g = gx * 64 + m;
            Bs[lk][m] = (g < G3 && kk < E) ? wih[(size_t)g * E + kk] : 0.f;
        }
        __syncthreads();
        #pragma unroll
        for (int k = 0; k < 16; ++k) {
            float a[4], bq[4];
            #pragma unroll
            for (int i = 0; i < 4; ++i) a[i]  = As[k][ty * 4 + i];
            #pragma unroll
            for (int j = 0; j < 4; ++j) bq[j] = Bs[k][tx * 4 + j];
            #pragma unroll
            for (int i = 0; i < 4; ++i)
                #pragma unroll
                for (int j = 0; j < 4; ++j) c[i][j] += a[i] * bq[j];
        }
        __syncthreads();
    }

    #pragma unroll
    for (int i = 0; i < 4; ++i) {
        int row = by * 64 + ty * 4 + i;
        #pragma unroll
        for (int j = 0; j < 4; ++j) {
            int g = gx * 64 + tx * 4 + j;
            if (g < G3)
                g_gi[((size_t)d * ROWS + row) * G3 + g] = c[i][j] + bih[g];
        }
    }
}

// ---------------- GRU recurrence: one block per (dir, batch) chain ----------
__global__ void __launch_bounds__(320, 1)
gru_recurrence(const float* __restrict__ bhh_f, const float* __restrict__ bhh_b,
               const float* __restrict__ h0_f,  const float* __restrict__ h0_b) {
    extern __shared__ float sm[];
    float* wc  = sm;                    // [CROWS][G3]  cached weight rows
    float* hs  = sm + CROWS * G3;       // [H]
    float* gh  = hs + H;                // [G3] partial (kq=0)
    float* ghp = gh + G3;               // [G3] partial (kq=1)
    float* gir = ghp + G3;              // [G3] gi row
    float* bhs = gir + G3;              // [G3] b_hh

    const int tid = threadIdx.x;
    const int d = blockIdx.x >> 5;
    const int b = blockIdx.x & 31;
    const int kq = tid / 160;           // k-half: 0 -> k in [0,100), 1 -> [100,200)
    const int gq = tid % 160;           // 4 gate rows per thread (gq < 150)

    const float* wgd = g_wt + (size_t)d * H * G3;
    const float* bhh = d ? bhh_b : bhh_f;
    const float* h0  = d ? h0_b  : h0_f;

    // --- init: cache weight rows k in [0,44) U [100,144), biases, h0 ---
    for (int i = tid; i < CROWS * G3; i += 320) {
        int r = i / G3, g = i - r * G3;
        int k = (r < CKK) ? r : (100 + (r - CKK));
        wc[i] = wgd[k * G3 + g];
    }
    for (int i = tid; i < G3; i += 320) bhs[i] = bhh[i];
    if (tid < H) hs[tid] = (h0[b * H + tid] - 0.5f) * (1.0f / H);
    __syncthreads();

    const float* gi_base  = g_gi  + (size_t)(d * ROWS + b * S) * G3;
    float*       hid_base = g_hid + (size_t)(d * ROWS + b * S) * H;

    for (int t = 0; t < S; ++t) {
        const int s = d ? (S - 1 - t) : t;
        const float* gi_row = gi_base + (size_t)s * G3;

        // prefetch gi row into smem (consumed after the barrier)
        for (int i = tid; i < G3; i += 320) gir[i] = gi_row[i];

        if (gq < 150) {
            const int   g0    = gq * 4;
            const int   kbase = kq * 100;
            float ax = 0.f, ay = 0.f, az = 0.f, aw = 0.f;

            // cached half: kk in [0,44)
            const float* wcp = wc + (size_t)(kq * CKK) * G3 + g0;
            #pragma unroll 4
            for (int kk = 0; kk < CKK; kk += 4) {
                float4 hv = *(const float4*)&hs[kbase + kk];
                float4 w0 = *(const float4*)(wcp + (size_t)(kk + 0) * G3);
                float4 w1 = *(const float4*)(wcp + (size_t)(kk + 1) * G3);
                float4 w2 = *(const float4*)(wcp + (size_t)(kk + 2) * G3);
                float4 w3 = *(const float4*)(wcp + (size_t)(kk + 3) * G3);
                ax += w0.x * hv.x; ay += w0.y * hv.x; az += w0.z * hv.x; aw += w0.w * hv.x;
                ax += w1.x * hv.y; ay += w1.y * hv.y; az += w1.z * hv.y; aw += w1.w * hv.y;
                ax += w2.x * hv.z; ay += w2.y * hv.z; az += w2.z * hv.z; aw += w2.w * hv.z;
                ax += w3.x * hv.w; ay += w3.y * hv.w; az += w3.z * hv.w; aw += w3.w * hv.w;
            }
            // streamed half: kk in [44,100) from L2 (coalesced float4)
            const float* wgp = wgd + g0;
            #pragma unroll 2
            for (int kk = CKK; kk < 100; kk += 4) {
                const int k = kbase + kk;
                float4 hv = *(const float4*)&hs[k];
                float4 w0 = *(const float4*)(wgp + (size_t)(k + 0) * G3);
                float4 w1 = *(const float4*)(wgp + (size_t)(k + 1) * G3);
                float4 w2 = *(const float4*)(wgp + (size_t)(k + 2) * G3);
                float4 w3 = *(const float4*)(wgp + (size_t)(k + 3) * G3);
                ax += w0.x * hv.x; ay += w0.y * hv.x; az += w0.z * hv.x; aw += w0.w * hv.x;
                ax += w1.x * hv.y; ay += w1.y * hv.y; az += w1.z * hv.y; aw += w1.w * hv.y;
                ax += w2.x * hv.z; ay += w2.y * hv.z; az += w2.z * hv.z; aw += w2.w * hv.z;
                ax += w3.x * hv.w; ay += w3.y * hv.w; az += w3.z * hv.w; aw += w3.w * hv.w;
            }
            float4 res = make_float4(ax, ay, az, aw);
            if (kq == 0) *(float4*)&gh [g0] = res;
            else         *(float4*)&ghp[g0] = res;
        }
        __syncthreads();

        // gates: PyTorch order (r, z, n)
        if (tid < H) {
            const int j = tid;
            float hr = gh[j]         + ghp[j]         + bhs[j];
            float hz = gh[H + j]     + ghp[H + j]     + bhs[H + j];
            float hn = gh[2 * H + j] + ghp[2 * H + j] + bhs[2 * H + j];
            float r = 1.f / (1.f + __expf(-(gir[j]         + hr)));
            float z = 1.f / (1.f + __expf(-(gir[H + j]     + hz)));
            float n = tanhf(gir[2 * H + j] + r * hn);
            float hv = (1.f - z) * n + z * hs[j];
            hs[j] = hv;
            hid_base[(size_t)s * H + j] = hv;
        }
        __syncthreads();
    }
}

// ---------------- final linear: warp per (b,s) row ----------
__global__ void preds_kernel(const float* __restrict__ lin_w,
                             const float* __restrict__ lin_b,
                             float* __restrict__ out) {
    __shared__ float lw[LBL * 2 * H];
    __shared__ float lb[LBL];
    const int tid = threadIdx.x;
    for (int i = tid; i < LBL * 2 * H; i += 256) lw[i] = lin_w[i];
    if (tid < LBL) lb[tid] = lin_b[tid];
    __syncthreads();

    const int wid = tid >> 5, lane = tid & 31;
    const int row = blockIdx.x * 8 + wid;
    const float* hf = g_hid + (size_t)row * H;
    const float* hb = g_hid + (size_t)(ROWS + row) * H;

    float acc[LBL] = {};
    for (int k = lane; k < 2 * H; k += 32) {
        float x = (k < H) ? hf[k] : hb[k - H];
        #pragma unroll
        for (int l = 0; l < LBL; ++l) acc[l] += x * lw[l * 2 * H + k];
    }
    #pragma unroll
    for (int l = 0; l < LBL; ++l) {
        float v = acc[l];
        #pragma unroll
        for (int o = 16; o > 0; o >>= 1) v += __shfl_xor_sync(0xffffffffu, v, o);
        if (lane == 0) out[(size_t)row * LBL + l] = v + lb[l];
    }
}

// ---------------- launch ----------
extern "C" void kernel_launch(void* const* d_in, const int* in_sizes, int n_in,
                              void* d_out, int out_size) {
    const int*   text  = (const int*)  d_in[0];
    const float* emb   = (const float*)d_in[1];
    const float* wih_f = (const float*)d_in[2];
    const float* whh_f = (const float*)d_in[3];
    const float* bih_f = (const float*)d_in[4];
    const float* bhh_f = (const float*)d_in[5];
    const float* wih_b = (const float*)d_in[6];
    const float* whh_b = (const float*)d_in[7];
    const float* bih_b = (const float*)d_in[8];
    const float* bhh_b = (const float*)d_in[9];
    const float* lin_w = (const float*)d_in[10];
    const float* lin_b = (const float*)d_in[11];
    const float* h0_f  = (const float*)d_in[12];
    const float* h0_b  = (const float*)d_in[13];
    float* out = (float*)d_out;

    prep_transpose<<<(G3 * H + 255) / 256, 256>>>(whh_f, whh_b);

    dim3 gg((G3 + 63) / 64, ROWS / 64, 2);
    gi_gemm<<<gg, 256>>>(text, emb, wih_f, bih_f, wih_b, bih_b);

    const int smem = (CROWS * G3 + H + 4 * G3) * 4;   // 221600 B
    cudaFuncSetAttribute(gru_recurrence,
                         cudaFuncAttributeMaxDynamicSharedMemorySize, smem);
    gru_recurrence<<<64, 320, smem>>>(bhh_f, bhh_b, h0_f, h0_b);

    preds_kernel<<<ROWS / 8, 256>>>(lin_w, lin_b, out);
}

// round 2
// speedup vs baseline: 1.0624x; 1.0624x over previous
#include <cuda_runtime.h>
#include <cstddef>

#define B   32
#define S   512
#define E   300
#define H   200
#define G3  600          // 3*H gate rows
#define LBL 10
#define ROWS (B*S)       // 16384

#define CKK   44         // cached kk per k-half (recurrence)
#define CROWS (2*CKK)

#define KT   16
#define PADW 132

typedef unsigned long long u64;

// ---------------- scratch (device globals: no allocations allowed) ----------
__device__ float g_gi [2u*ROWS*(size_t)G3];   // [dir][b*S+s][g]  ~78.6 MB
__device__ float g_wt [2*H*G3];               // w_hh transposed: [dir][k][g]
__device__ float g_hid[2u*ROWS*(size_t)H];    // hidden outputs   ~26.2 MB

// ---------------- f32x2 packed helpers ----------
__device__ __forceinline__ u64 pack2(float x, float y) {
    u64 r; asm("mov.b64 %0, {%1,%2};" : "=l"(r) : "f"(x), "f"(y)); return r;
}
__device__ __forceinline__ void unpack2(u64 v, float& x, float& y) {
    asm("mov.b64 {%0,%1}, %2;" : "=f"(x), "=f"(y) : "l"(v));
}
__device__ __forceinline__ void ffma2(u64& d, u64 a, u64 b) {
    asm("fma.rn.f32x2 %0, %1, %2, %0;" : "+l"(d) : "l"(a), "l"(b));
}

// ---------------- prep: transpose w_hh into [k][g] ----------
__global__ void prep_transpose(const float* __restrict__ wf,
                               const float* __restrict__ wb) {
    int i = blockIdx.x * blockDim.x + threadIdx.x;
    if (i < G3 * H) {
        int g = i / H, k = i - g * H;
        g_wt[k * G3 + g]          = wf[i];
        g_wt[H * G3 + k * G3 + g] = wb[i];
    }
}

// ---------------- gi = emb[text] @ w_ih^T + b_ih  (128x128 FFMA2 tiles) ----
__global__ void __launch_bounds__(256)
gi_gemm2(const int*   __restrict__ text,
         const float* __restrict__ emb,
         const float* __restrict__ wih_f,
         const float* __restrict__ bih_f,
         const float* __restrict__ wih_b,
         const float* __restrict__ bih_b) {
    const int d = blockIdx.z;
    const float* __restrict__ wih = d ? wih_b : wih_f;
    const float* __restrict__ bih = d ? bih_b : bih_f;

    __shared__ float As[KT][PADW];   // [k][m]
    __shared__ float Bs[KT][PADW];   // [k][n]
    __shared__ int   tok[128];

    const int tid = threadIdx.x;
    const int by  = blockIdx.y;          // m tile (128 rows)
    const int n0  = blockIdx.x * 128;    // n tile base

    if (tid < 128) tok[tid] = text[by * 128 + tid];
    __syncthreads();

    // loader mapping: each thread owns (kq, m0) and (kq, m0+64)
    const int kq = tid & 3;              // which float4 of the 16-k tile
    const int m0 = tid >> 2;             // 0..63
    const int m1 = m0 + 64;
    const long ar0 = (long)tok[m0] * E;
    const long ar1 = (long)tok[m1] * E;
    const int  g0  = n0 + m0, g1 = n0 + m1;
    const bool vg0 = g0 < G3, vg1 = g1 < G3;

    const int ty = tid >> 4, tx = tid & 15;   // 16x16 compute grid, 8x8 each

    u64 acc[8][4];
    #pragma unroll
    for (int i = 0; i < 8; ++i)
        #pragma unroll
        for (int j = 0; j < 4; ++j) acc[i][j] = 0ULL;

    const float4 z4 = make_float4(0.f, 0.f, 0.f, 0.f);
    float4 aV0, aV1, bV0, bV1;

    // prologue: prefetch tile 0 (kk = kq*4 < 16 <= E always valid)
    {
        const int kk = kq * 4;
        aV0 = *(const float4*)&emb[ar0 + kk];
        aV1 = *(const float4*)&emb[ar1 + kk];
        bV0 = vg0 ? *(const float4*)&wih[(size_t)g0 * E + kk] : z4;
        bV1 = vg1 ? *(const float4*)&wih[(size_t)g1 * E + kk] : z4;
    }

    const int NT = (E + KT - 1) / KT;    // 19 (K padded to 304 with zeros)
    for (int t = 0; t < NT; ++t) {
        __syncthreads();                 // previous compute done
        As[kq*4+0][m0] = aV0.x; As[kq*4+1][m0] = aV0.y;
        As[kq*4+2][m0] = aV0.z; As[kq*4+3][m0] = aV0.w;
        As[kq*4+0][m1] = aV1.x; As[kq*4+1][m1] = aV1.y;
        As[kq*4+2][m1] = aV1.z; As[kq*4+3][m1] = aV1.w;
        Bs[kq*4+0][m0] = bV0.x; Bs[kq*4+1][m0] = bV0.y;
        Bs[kq*4+2][m0] = bV0.z; Bs[kq*4+3][m0] = bV0.w;
        Bs[kq*4+0][m1] = bV1.x; Bs[kq*4+1][m1] = bV1.y;
        Bs[kq*4+2][m1] = bV1.z; Bs[kq*4+3][m1] = bV1.w;
        __syncthreads();

        if (t + 1 < NT) {                // register prefetch of next tile
            const int kk = (t + 1) * KT + kq * 4;
            const bool vk = kk < E;      // tail: kq==3 of last tile invalid
            aV0 = vk ? *(const float4*)&emb[ar0 + kk] : z4;
            aV1 = vk ? *(const float4*)&emb[ar1 + kk] : z4;
            bV0 = (vk && vg0) ? *(const float4*)&wih[(size_t)g0 * E + kk] : z4;
            bV1 = (vk && vg1) ? *(const float4*)&wih[(size_t)g1 * E + kk] : z4;
        }

        #pragma unroll
        for (int k = 0; k < KT; ++k) {
            float4 a0 = *(const float4*)&As[k][ty * 8];
            float4 a1 = *(const float4*)&As[k][ty * 8 + 4];
            float4 b0 = *(const float4*)&Bs[k][tx * 8];
            float4 b1 = *(const float4*)&Bs[k][tx * 8 + 4];
            u64 bp[4] = { pack2(b0.x, b0.y), pack2(b0.z, b0.w),
                          pack2(b1.x, b1.y), pack2(b1.z, b1.w) };
            float av[8] = { a0.x, a0.y, a0.z, a0.w, a1.x, a1.y, a1.z, a1.w };
            #pragma unroll
            for (int i = 0; i < 8; ++i) {
                u64 ap = pack2(av[i], av[i]);
                #pragma unroll
                for (int j = 0; j < 4; ++j) ffma2(acc[i][j], ap, bp[j]);
            }
        }
    }

    // epilogue: add bias, store
    float* gout = g_gi + (size_t)d * ROWS * G3;
    #pragma unroll
    for (int i = 0; i < 8; ++i) {
        const int row = by * 128 + ty * 8 + i;
        float o[8];
        #pragma unroll
        for (int j = 0; j < 4; ++j) unpack2(acc[i][j], o[2*j], o[2*j+1]);
        #pragma unroll
        for (int j = 0; j < 8; ++j) {
            const int g = n0 + tx * 8 + j;
            if (g < G3)
                gout[(size_t)row * G3 + g] = o[j] + bih[g];
        }
    }
}

// ---------------- GRU recurrence: one block per (dir, batch) chain ----------
__global__ void __launch_bounds__(320, 1)
gru_recurrence(const float* __restrict__ bhh_f, const float* __restrict__ bhh_b,
               const float* __restrict__ h0_f,  const float* __restrict__ h0_b) {
    extern __shared__ float sm[];
    float* wc  = sm;                    // [CROWS][G3]  cached weight rows
    float* hs  = sm + CROWS * G3;       // [H]
    float* gh  = hs + H;                // [G3] partial (kq=0)
    float* ghp = gh + G3;               // [G3] partial (kq=1)
    float* gir = ghp + G3;              // [G3] gi row
    float* bhs = gir + G3;              // [G3] b_hh

    const int tid = threadIdx.x;
    const int d = blockIdx.x >> 5;
    const int b = blockIdx.x & 31;
    const int kq = tid / 160;           // k-half
    const int gq = tid % 160;

    const float* wgd = g_wt + (size_t)d * H * G3;
    const float* bhh = d ? bhh_b : bhh_f;
    const float* h0  = d ? h0_b  : h0_f;

    for (int i = tid; i < CROWS * G3; i += 320) {
        int r = i / G3, g = i - r * G3;
        int k = (r < CKK) ? r : (100 + (r - CKK));
        wc[i] = wgd[k * G3 + g];
    }
    for (int i = tid; i < G3; i += 320) bhs[i] = bhh[i];
    if (tid < H) hs[tid] = (h0[b * H + tid] - 0.5f) * (1.0f / H);
    __syncthreads();

    const float* gi_base  = g_gi  + (size_t)(d * ROWS + b * S) * G3;
    float*       hid_base = g_hid + (size_t)(d * ROWS + b * S) * H;

    for (int t = 0; t < S; ++t) {
        const int s = d ? (S - 1 - t) : t;
        const float* gi_row = gi_base + (size_t)s * G3;

        for (int i = tid; i < G3; i += 320) gir[i] = gi_row[i];

        if (gq < 150) {
            const int   g0    = gq * 4;
            const int   kbase = kq * 100;
            float ax = 0.f, ay = 0.f, az = 0.f, aw = 0.f;

            const float* wcp = wc + (size_t)(kq * CKK) * G3 + g0;
            #pragma unroll 4
            for (int kk = 0; kk < CKK; kk += 4) {
                float4 hv = *(const float4*)&hs[kbase + kk];
                float4 w0 = *(const float4*)(wcp + (size_t)(kk + 0) * G3);
                float4 w1 = *(const float4*)(wcp + (size_t)(kk + 1) * G3);
                float4 w2 = *(const float4*)(wcp + (size_t)(kk + 2) * G3);
                float4 w3 = *(const float4*)(wcp + (size_t)(kk + 3) * G3);
                ax += w0.x * hv.x; ay += w0.y * hv.x; az += w0.z * hv.x; aw += w0.w * hv.x;
                ax += w1.x * hv.y; ay += w1.y * hv.y; az += w1.z * hv.y; aw += w1.w * hv.y;
                ax += w2.x * hv.z; ay += w2.y * hv.z; az += w2.z * hv.z; aw += w2.w * hv.z;
                ax += w3.x * hv.w; ay += w3.y * hv.w; az += w3.z * hv.w; aw += w3.w * hv.w;
            }
            const float* wgp = wgd + g0;
            #pragma unroll 2
            for (int kk = CKK; kk < 100; kk += 4) {
                const int k = kbase + kk;
                float4 hv = *(const float4*)&hs[k];
                float4 w0 = *(const float4*)(wgp + (size_t)(k + 0) * G3);
                float4 w1 = *(const float4*)(wgp + (size_t)(k + 1) * G3);
                float4 w2 = *(const float4*)(wgp + (size_t)(k + 2) * G3);
                float4 w3 = *(const float4*)(wgp + (size_t)(k + 3) * G3);
                ax += w0.x * hv.x; ay += w0.y * hv.x; az += w0.z * hv.x; aw += w0.w * hv.x;
                ax += w1.x * hv.y; ay += w1.y * hv.y; az += w1.z * hv.y; aw += w1.w * hv.y;
                ax += w2.x * hv.z; ay += w2.y * hv.z; az += w2.z * hv.z; aw += w2.w * hv.z;
                ax += w3.x * hv.w; ay += w3.y * hv.w; az += w3.z * hv.w; aw += w3.w * hv.w;
            }
            float4 res = make_float4(ax, ay, az, aw);
            if (kq == 0) *(float4*)&gh [g0] = res;
            else         *(float4*)&ghp[g0] = res;
        }
        __syncthreads();

        if (tid < H) {
            const int j = tid;
            float hr = gh[j]         + ghp[j]         + bhs[j];
            float hz = gh[H + j]     + ghp[H + j]     + bhs[H + j];
            float hn = gh[2 * H + j] + ghp[2 * H + j] + bhs[2 * H + j];
            float r = 1.f / (1.f + __expf(-(gir[j]         + hr)));
            float z = 1.f / (1.f + __expf(-(gir[H + j]     + hz)));
            float n = tanhf(gir[2 * H + j] + r * hn);
            float hv = (1.f - z) * n + z * hs[j];
            hs[j] = hv;
            hid_base[(size_t)s * H + j] = hv;
        }
        __syncthreads();
    }
}

// ---------------- final linear: warp per (b,s) row ----------
__global__ void preds_kernel(const float* __restrict__ lin_w,
                             const float* __restrict__ lin_b,
                             float* __restrict__ out) {
    __shared__ float lw[LBL * 2 * H];
    __shared__ float lb[LBL];
    const int tid = threadIdx.x;
    for (int i = tid; i < LBL * 2 * H; i += 256) lw[i] = lin_w[i];
    if (tid < LBL) lb[tid] = lin_b[tid];
    __syncthreads();

    const int wid = tid >> 5, lane = tid & 31;
    const int row = blockIdx.x * 8 + wid;
    const float* hf = g_hid + (size_t)row * H;
    const float* hb = g_hid + (size_t)(ROWS + row) * H;

    float acc[LBL] = {};
    for (int k = lane; k < 2 * H; k += 32) {
        float x = (k < H) ? hf[k] : hb[k - H];
        #pragma unroll
        for (int l = 0; l < LBL; ++l) acc[l] += x * lw[l * 2 * H + k];
    }
    #pragma unroll
    for (int l = 0; l < LBL; ++l) {
        float v = acc[l];
        #pragma unroll
        for (int o = 16; o > 0; o >>= 1) v += __shfl_xor_sync(0xffffffffu, v, o);
        if (lane == 0) out[(size_t)row * LBL + l] = v + lb[l];
    }
}

// ---------------- launch ----------
extern "C" void kernel_launch(void* const* d_in, const int* in_sizes, int n_in,
                              void* d_out, int out_size) {
    const int*   text  = (const int*)  d_in[0];
    const float* emb   = (const float*)d_in[1];
    const float* wih_f = (const float*)d_in[2];
    const float* whh_f = (const float*)d_in[3];
    const float* bih_f = (const float*)d_in[4];
    const float* bhh_f = (const float*)d_in[5];
    const float* wih_b = (const float*)d_in[6];
    const float* whh_b = (const float*)d_in[7];
    const float* bih_b = (const float*)d_in[8];
    const float* bhh_b = (const float*)d_in[9];
    const float* lin_w = (const float*)d_in[10];
    const float* lin_b = (const float*)d_in[11];
    const float* h0_f  = (const float*)d_in[12];
    const float* h0_b  = (const float*)d_in[13];
    float* out = (float*)d_out;

    prep_transpose<<<(G3 * H + 255) / 256, 256>>>(whh_f, whh_b);

    dim3 gg((G3 + 127) / 128, ROWS / 128, 2);   // (5, 128, 2)
    gi_gemm2<<<gg, 256>>>(text, emb, wih_f, bih_f, wih_b, bih_b);

    const int smem = (CROWS * G3 + H + 4 * G3) * 4;   // 221600 B
    cudaFuncSetAttribute(gru_recurrence,
                         cudaFuncAttributeMaxDynamicSharedMemorySize, smem);
    gru_recurrence<<<64, 320, smem>>>(bhh_f, bhh_b, h0_f, h0_b);

    preds_kernel<<<ROWS / 8, 256>>>(lin_w, lin_b, out);
}

// round 3
// speedup vs baseline: 1.8612x; 1.7518x over previous
#include <cuda_runtime.h>
#include <cstddef>
#include <cstdint>

#define B   32
#define S   512
#define E   300
#define H   200
#define G3  600          // 3*H gate rows
#define GS  200          // gate slice per cluster CTA
#define LBL 10
#define ROWS (B*S)       // 16384

#define KT   16
#define PADW 132

typedef unsigned long long u64;

// ---------------- scratch (device globals: no allocations allowed) ----------
__device__ float g_gi [2u*ROWS*(size_t)G3];   // [dir][b*S+s][g]  ~78.6 MB
__device__ float g_wt [2*H*G3];               // w_hh transposed: [dir][k][g]
__device__ float g_hid[2u*ROWS*(size_t)H];    // hidden outputs   ~26.2 MB

// ---------------- f32x2 packed helpers ----------
__device__ __forceinline__ u64 pack2(float x, float y) {
    u64 r; asm("mov.b64 %0, {%1,%2};" : "=l"(r) : "f"(x), "f"(y)); return r;
}
__device__ __forceinline__ void unpack2(u64 v, float& x, float& y) {
    asm("mov.b64 {%0,%1}, %2;" : "=f"(x), "=f"(y) : "l"(v));
}
__device__ __forceinline__ void ffma2(u64& d, u64 a, u64 b) {
    asm("fma.rn.f32x2 %0, %1, %2, %0;" : "+l"(d) : "l"(a), "l"(b));
}

// ---------------- cluster / DSMEM helpers ----------
__device__ __forceinline__ uint32_t s2u(const void* p) {
    uint32_t a;
    asm("{ .reg .u64 t; cvta.to.shared.u64 t, %1; cvt.u32.u64 %0, t; }"
        : "=r"(a) : "l"(p));
    return a;
}
__device__ __forceinline__ uint32_t mapa_u32(uint32_t a, uint32_t r) {
    uint32_t o;
    asm("mapa.shared::cluster.u32 %0, %1, %2;" : "=r"(o) : "r"(a), "r"(r));
    return o;
}
__device__ __forceinline__ void stc64(uint32_t a, u64 v) {
    asm volatile("st.shared::cluster.b64 [%0], %1;" :: "r"(a), "l"(v) : "memory");
}
__device__ __forceinline__ uint32_t ctarank() {
    uint32_t r; asm("mov.u32 %0, %%cluster_ctarank;" : "=r"(r)); return r;
}
#define CLUSTER_SYNC() do { \
    asm volatile("barrier.cluster.arrive.aligned;" ::: "memory"); \
    asm volatile("barrier.cluster.wait.aligned;" ::: "memory");   \
} while (0)

// ---------------- prep: transpose w_hh into [k][g] ----------
__global__ void prep_transpose(const float* __restrict__ wf,
                               const float* __restrict__ wb) {
    int i = blockIdx.x * blockDim.x + threadIdx.x;
    if (i < G3 * H) {
        int g = i / H, k = i - g * H;
        g_wt[k * G3 + g]          = wf[i];
        g_wt[H * G3 + k * G3 + g] = wb[i];
    }
}

// ---------------- gi = emb[text] @ w_ih^T + b_ih  (128x128 FFMA2 tiles) ----
__global__ void __launch_bounds__(256)
gi_gemm2(const int*   __restrict__ text,
         const float* __restrict__ emb,
         const float* __restrict__ wih_f,
         const float* __restrict__ bih_f,
         const float* __restrict__ wih_b,
         const float* __restrict__ bih_b) {
    const int d = blockIdx.z;
    const float* __restrict__ wih = d ? wih_b : wih_f;
    const float* __restrict__ bih = d ? bih_b : bih_f;

    __shared__ float As[KT][PADW];   // [k][m]
    __shared__ float Bs[KT][PADW];   // [k][n]
    __shared__ int   tok[128];

    const int tid = threadIdx.x;
    const int by  = blockIdx.y;
    const int n0  = blockIdx.x * 128;

    if (tid < 128) tok[tid] = text[by * 128 + tid];
    __syncthreads();

    const int kq = tid & 3;
    const int m0 = tid >> 2;
    const int m1 = m0 + 64;
    const long ar0 = (long)tok[m0] * E;
    const long ar1 = (long)tok[m1] * E;
    const int  g0  = n0 + m0, g1 = n0 + m1;
    const bool vg0 = g0 < G3, vg1 = g1 < G3;

    const int ty = tid >> 4, tx = tid & 15;

    u64 acc[8][4];
    #pragma unroll
    for (int i = 0; i < 8; ++i)
        #pragma unroll
        for (int j = 0; j < 4; ++j) acc[i][j] = 0ULL;

    const float4 z4 = make_float4(0.f, 0.f, 0.f, 0.f);
    float4 aV0, aV1, bV0, bV1;

    {
        const int kk = kq * 4;
        aV0 = *(const float4*)&emb[ar0 + kk];
        aV1 = *(const float4*)&emb[ar1 + kk];
        bV0 = vg0 ? *(const float4*)&wih[(size_t)g0 * E + kk] : z4;
        bV1 = vg1 ? *(const float4*)&wih[(size_t)g1 * E + kk] : z4;
    }

    const int NT = (E + KT - 1) / KT;    // 19
    for (int t = 0; t < NT; ++t) {
        __syncthreads();
        As[kq*4+0][m0] = aV0.x; As[kq*4+1][m0] = aV0.y;
        As[kq*4+2][m0] = aV0.z; As[kq*4+3][m0] = aV0.w;
        As[kq*4+0][m1] = aV1.x; As[kq*4+1][m1] = aV1.y;
        As[kq*4+2][m1] = aV1.z; As[kq*4+3][m1] = aV1.w;
        Bs[kq*4+0][m0] = bV0.x; Bs[kq*4+1][m0] = bV0.y;
        Bs[kq*4+2][m0] = bV0.z; Bs[kq*4+3][m0] = bV0.w;
        Bs[kq*4+0][m1] = bV1.x; Bs[kq*4+1][m1] = bV1.y;
        Bs[kq*4+2][m1] = bV1.z; Bs[kq*4+3][m1] = bV1.w;
        __syncthreads();

        if (t + 1 < NT) {
            const int kk = (t + 1) * KT + kq * 4;
            const bool vk = kk < E;
            aV0 = vk ? *(const float4*)&emb[ar0 + kk] : z4;
            aV1 = vk ? *(const float4*)&emb[ar1 + kk] : z4;
            bV0 = (vk && vg0) ? *(const float4*)&wih[(size_t)g0 * E + kk] : z4;
            bV1 = (vk && vg1) ? *(const float4*)&wih[(size_t)g1 * E + kk] : z4;
        }

        #pragma unroll
        for (int k = 0; k < KT; ++k) {
            float4 a0 = *(const float4*)&As[k][ty * 8];
            float4 a1 = *(const float4*)&As[k][ty * 8 + 4];
            float4 b0 = *(const float4*)&Bs[k][tx * 8];
            float4 b1 = *(const float4*)&Bs[k][tx * 8 + 4];
            u64 bp[4] = { pack2(b0.x, b0.y), pack2(b0.z, b0.w),
                          pack2(b1.x, b1.y), pack2(b1.z, b1.w) };
            float av[8] = { a0.x, a0.y, a0.z, a0.w, a1.x, a1.y, a1.z, a1.w };
            #pragma unroll
            for (int i = 0; i < 8; ++i) {
                u64 ap = pack2(av[i], av[i]);
                #pragma unroll
                for (int j = 0; j < 4; ++j) ffma2(acc[i][j], ap, bp[j]);
            }
        }
    }

    float* gout = g_gi + (size_t)d * ROWS * G3;
    #pragma unroll
    for (int i = 0; i < 8; ++i) {
        const int row = by * 128 + ty * 8 + i;
        float o[8];
        #pragma unroll
        for (int j = 0; j < 4; ++j) unpack2(acc[i][j], o[2*j], o[2*j+1]);
        #pragma unroll
        for (int j = 0; j < 8; ++j) {
            const int g = n0 + tx * 8 + j;
            if (g < G3)
                gout[(size_t)row * G3 + g] = o[j] + bih[g];
        }
    }
}

// ---------------- GRU recurrence: 3-CTA cluster per 2 chains (g-split) -----
// rank 0 -> r-gate rows [0,200), rank 1 -> z [200,400), rank 2 -> n [400,600)
// smem (floats): wsm[0,40000) | hsd0 u64[200] @40000 | hsd1 @40400
//                red0[8*200) @40800 | red1 @42400
//                mail float2[2buf][2comp][600] @44000 (4800 floats)
//                bo[200] @48800   -> total 49000 floats = 196000 B
__global__ void __launch_bounds__(512, 1) __cluster_dims__(3, 1, 1)
gru_rec3(const float* __restrict__ bhh_f, const float* __restrict__ bhh_b,
         const float* __restrict__ h0_f,  const float* __restrict__ h0_b) {
    extern __shared__ float sm[];
    float*  wsm  = sm;                       // [200k][200g]
    u64*    hsd0 = (u64*)(sm + 40000);       // (h,h) per k, batch 0
    u64*    hsd1 = (u64*)(sm + 40400);       // batch 1
    float*  red0 = sm + 40800;               // [8 kq][200 g]
    float*  red1 = sm + 42400;
    float2* mail = (float2*)(sm + 44000);    // [(buf*2+comp)*600 + g]
    float*  bo   = sm + 48800;               // b_hh slice

    const int tid = threadIdx.x;
    const uint32_t rank = ctarank();
    const int group = blockIdx.x / 3;
    const int d  = group >> 4;
    const int b0 = (group & 15) * 2, b1 = b0 + 1;

    const float* bhh = d ? bhh_b : bhh_f;
    const float* h0  = d ? h0_b  : h0_f;

    // weights: own gate slice, [k][g] layout
    const float* wg = g_wt + (size_t)d * (H * G3) + rank * GS;
    for (int i = tid; i < H * GS; i += 512)
        wsm[i] = wg[(size_t)(i / GS) * G3 + (i % GS)];
    if (tid < GS) {
        bo[tid] = bhh[rank * GS + tid];
        float a = (h0[b0 * H + tid] - 0.5f) * (1.0f / H);
        float c = (h0[b1 * H + tid] - 0.5f) * (1.0f / H);
        hsd0[tid] = pack2(a, a);
        hsd1[tid] = pack2(c, c);
    }
    __syncthreads();

    const size_t gib0 = ((size_t)d * ROWS + (size_t)b0 * S) * G3 + rank * GS;
    const size_t gib1 = ((size_t)d * ROWS + (size_t)b1 * S) * G3 + rank * GS;
    float* hid0 = g_hid + ((size_t)d * ROWS + (size_t)b0 * S) * H;
    float* hid1 = g_hid + ((size_t)d * ROWS + (size_t)b1 * S) * H;

    const uint32_t mail_u = s2u(mail);
    const uint32_t pr0 = (rank + 1) % 3, pr1 = (rank + 2) % 3;

    const int g4 = tid % 50;      // g quad (tid<400)
    const int kq = tid / 50;      // k chunk of 25

    for (int t = 0; t < S; ++t) {
        const int s = d ? (S - 1 - t) : t;

        // gi prefetch (overlaps matvec)
        float gia = 0.f, gib = 0.f;
        if (tid < GS) {
            gia = g_gi[gib0 + (size_t)s * G3 + tid];
            gib = g_gi[gib1 + (size_t)s * G3 + tid];
        }

        // matvec: gh[g] = sum_k w[k][g] * h[k], both batches f32x2-packed
        if (tid < 400) {
            const float* wp  = wsm + kq * 25 * GS + g4 * 4;
            const u64*   hp0 = hsd0 + kq * 25;
            const u64*   hp1 = hsd1 + kq * 25;
            u64 a00 = 0, a01 = 0, a10 = 0, a11 = 0;
            #pragma unroll
            for (int kk = 0; kk < 25; ++kk) {
                float4 w = *(const float4*)(wp + kk * GS);
                u64 w01 = pack2(w.x, w.y), w23 = pack2(w.z, w.w);
                u64 hb0 = hp0[kk], hb1 = hp1[kk];
                ffma2(a00, w01, hb0); ffma2(a01, w23, hb0);
                ffma2(a10, w01, hb1); ffma2(a11, w23, hb1);
            }
            float x0, y0, x1, y1;
            unpack2(a00, x0, y0); unpack2(a01, x1, y1);
            *(float4*)&red0[kq * GS + g4 * 4] = make_float4(x0, y0, x1, y1);
            unpack2(a10, x0, y0); unpack2(a11, x1, y1);
            *(float4*)&red1[kq * GS + g4 * 4] = make_float4(x0, y0, x1, y1);
        }
        __syncthreads();

        const int buf = t & 1;
        if (tid < GS) {
            float s0 = 0.f, s1 = 0.f;
            #pragma unroll
            for (int q = 0; q < 8; ++q) {
                s0 += red0[q * GS + tid];
                s1 += red1[q * GS + tid];
            }
            float2 ch = make_float2(s0 + bo[tid], s1 + bo[tid]);  // gh + b_hh
            float2 ci = make_float2(gia, gib);                    // gi
            const int g = rank * GS + tid;
            mail[(buf * 2 + 0) * G3 + g] = ch;
            mail[(buf * 2 + 1) * G3 + g] = ci;
            const uint32_t ah = mail_u + (uint32_t)(((buf * 2 + 0) * G3 + g) * 8);
            const uint32_t ai = mail_u + (uint32_t)(((buf * 2 + 1) * G3 + g) * 8);
            const u64 chu = pack2(ch.x, ch.y);
            const u64 ciu = pack2(ci.x, ci.y);
            stc64(mapa_u32(ah, pr0), chu);
            stc64(mapa_u32(ah, pr1), chu);
            stc64(mapa_u32(ai, pr0), ciu);
            stc64(mapa_u32(ai, pr1), ciu);
        }
        CLUSTER_SYNC();   // arrive=release, wait=acquire: pushes visible

        if (tid < GS) {
            const float2* mc = mail + (buf * 2 + 0) * G3;
            const float2* mi = mail + (buf * 2 + 1) * G3;
            float2 chr = mc[tid],        cir  = mi[tid];
            float2 chz = mc[H + tid],    ciz  = mi[H + tid];
            float2 chn = mc[2*H + tid],  cin_ = mi[2*H + tid];
            float r0 = 1.f / (1.f + __expf(-(cir.x + chr.x)));
            float r1 = 1.f / (1.f + __expf(-(cir.y + chr.y)));
            float z0 = 1.f / (1.f + __expf(-(ciz.x + chz.x)));
            float z1 = 1.f / (1.f + __expf(-(ciz.y + chz.y)));
            float n0 = tanhf(cin_.x + r0 * chn.x);
            float n1 = tanhf(cin_.y + r1 * chn.y);
            float ho0, ho1, dummy;
            unpack2(hsd0[tid], ho0, dummy);
            unpack2(hsd1[tid], ho1, dummy);
            float hn0 = (1.f - z0) * n0 + z0 * ho0;
            float hn1 = (1.f - z1) * n1 + z1 * ho1;
            hsd0[tid] = pack2(hn0, hn0);
            hsd1[tid] = pack2(hn1, hn1);
            if (rank == 0) {
                hid0[(size_t)s * H + tid] = hn0;
                hid1[(size_t)s * H + tid] = hn1;
            }
        }
        __syncthreads();
    }
}

// ---------------- final linear: warp per (b,s) row ----------
__global__ void preds_kernel(const float* __restrict__ lin_w,
                             const float* __restrict__ lin_b,
                             float* __restrict__ out) {
    __shared__ float lw[LBL * 2 * H];
    __shared__ float lb[LBL];
    const int tid = threadIdx.x;
    for (int i = tid; i < LBL * 2 * H; i += 256) lw[i] = lin_w[i];
    if (tid < LBL) lb[tid] = lin_b[tid];
    __syncthreads();

    const int wid = tid >> 5, lane = tid & 31;
    const int row = blockIdx.x * 8 + wid;
    const float* hf = g_hid + (size_t)row * H;
    const float* hb = g_hid + (size_t)(ROWS + row) * H;

    float acc[LBL] = {};
    for (int k = lane; k < 2 * H; k += 32) {
        float x = (k < H) ? hf[k] : hb[k - H];
        #pragma unroll
        for (int l = 0; l < LBL; ++l) acc[l] += x * lw[l * 2 * H + k];
    }
    #pragma unroll
    for (int l = 0; l < LBL; ++l) {
        float v = acc[l];
        #pragma unroll
        for (int o = 16; o > 0; o >>= 1) v += __shfl_xor_sync(0xffffffffu, v, o);
        if (lane == 0) out[(size_t)row * LBL + l] = v + lb[l];
    }
}

// ---------------- launch ----------
extern "C" void kernel_launch(void* const* d_in, const int* in_sizes, int n_in,
                              void* d_out, int out_size) {
    const int*   text  = (const int*)  d_in[0];
    const float* emb   = (const float*)d_in[1];
    const float* wih_f = (const float*)d_in[2];
    const float* whh_f = (const float*)d_in[3];
    const float* bih_f = (const float*)d_in[4];
    const float* bhh_f = (const float*)d_in[5];
    const float* wih_b = (const float*)d_in[6];
    const float* whh_b = (const float*)d_in[7];
    const float* bih_b = (const float*)d_in[8];
    const float* bhh_b = (const float*)d_in[9];
    const float* lin_w = (const float*)d_in[10];
    const float* lin_b = (const float*)d_in[11];
    const float* h0_f  = (const float*)d_in[12];
    const float* h0_b  = (const float*)d_in[13];
    float* out = (float*)d_out;

    prep_transpose<<<(G3 * H + 255) / 256, 256>>>(whh_f, whh_b);

    dim3 gg((G3 + 127) / 128, ROWS / 128, 2);   // (5, 128, 2)
    gi_gemm2<<<gg, 256>>>(text, emb, wih_f, bih_f, wih_b, bih_b);

    const int smem = 49000 * 4;                 // 196000 B
    cudaFuncSetAttribute(gru_rec3,
                         cudaFuncAttributeMaxDynamicSharedMemorySize, smem);
    gru_rec3<<<96, 512, smem>>>(bhh_f, bhh_b, h0_f, h0_b);

    preds_kernel<<<ROWS / 8, 256>>>(lin_w, lin_b, out);
}

// round 4
// speedup vs baseline: 1.9581x; 1.0521x over previous
#include <cuda_runtime.h>
#include <cstddef>
#include <cstdint>

#define B   32
#define S   512
#define E   300
#define H   200
#define G3  600          // 3*H gate rows
#define GS  200          // gate slice per cluster CTA
#define LBL 10
#define ROWS (B*S)       // 16384

#define KT   16
#define PADW 132

typedef unsigned long long u64;

// ---------------- scratch (device globals: no allocations allowed) ----------
__device__ float g_gi [2u*ROWS*(size_t)G3];   // [dir][b*S+s][g]  ~78.6 MB
__device__ float g_wt [2*H*G3];               // w_hh transposed: [dir][k][g]
__device__ float g_hid[2u*ROWS*(size_t)H];    // hidden outputs   ~26.2 MB

// ---------------- f32x2 packed helpers ----------
__device__ __forceinline__ u64 pack2(float x, float y) {
    u64 r; asm("mov.b64 %0, {%1,%2};" : "=l"(r) : "f"(x), "f"(y)); return r;
}
__device__ __forceinline__ void unpack2(u64 v, float& x, float& y) {
    asm("mov.b64 {%0,%1}, %2;" : "=f"(x), "=f"(y) : "l"(v));
}
__device__ __forceinline__ void ffma2(u64& d, u64 a, u64 b) {
    asm("fma.rn.f32x2 %0, %1, %2, %0;" : "+l"(d) : "l"(a), "l"(b));
}
__device__ __forceinline__ void add2(u64& d, u64 a) {
    asm("add.rn.f32x2 %0, %0, %1;" : "+l"(d) : "l"(a));
}

// ---------------- cluster / DSMEM helpers ----------
__device__ __forceinline__ uint32_t s2u(const void* p) {
    uint32_t a;
    asm("{ .reg .u64 t; cvta.to.shared.u64 t, %1; cvt.u32.u64 %0, t; }"
        : "=r"(a) : "l"(p));
    return a;
}
__device__ __forceinline__ uint32_t mapa_u32(uint32_t a, uint32_t r) {
    uint32_t o;
    asm("mapa.shared::cluster.u32 %0, %1, %2;" : "=r"(o) : "r"(a), "r"(r));
    return o;
}
__device__ __forceinline__ void stc64(uint32_t a, u64 v) {
    asm volatile("st.shared::cluster.b64 [%0], %1;" :: "r"(a), "l"(v) : "memory");
}
__device__ __forceinline__ uint32_t ctarank() {
    uint32_t r; asm("mov.u32 %0, %%cluster_ctarank;" : "=r"(r)); return r;
}
#define CLUSTER_SYNC() do { \
    asm volatile("barrier.cluster.arrive.aligned;" ::: "memory"); \
    asm volatile("barrier.cluster.wait.aligned;" ::: "memory");   \
} while (0)

// ---------------- prep: transpose w_hh into [k][g] ----------
__global__ void prep_transpose(const float* __restrict__ wf,
                               const float* __restrict__ wb) {
    int i = blockIdx.x * blockDim.x + threadIdx.x;
    if (i < G3 * H) {
        int g = i / H, k = i - g * H;
        g_wt[k * G3 + g]          = wf[i];
        g_wt[H * G3 + k * G3 + g] = wb[i];
    }
}

// ---------------- gi = emb[text] @ w_ih^T + b_ih  (128x128 FFMA2 tiles) ----
__global__ void __launch_bounds__(256)
gi_gemm2(const int*   __restrict__ text,
         const float* __restrict__ emb,
         const float* __restrict__ wih_f,
         const float* __restrict__ bih_f,
         const float* __restrict__ wih_b,
         const float* __restrict__ bih_b) {
    const int d = blockIdx.z;
    const float* __restrict__ wih = d ? wih_b : wih_f;
    const float* __restrict__ bih = d ? bih_b : bih_f;

    __shared__ float As[KT][PADW];   // [k][m]
    __shared__ float Bs[KT][PADW];   // [k][n]
    __shared__ int   tok[128];

    const int tid = threadIdx.x;
    const int by  = blockIdx.y;
    const int n0  = blockIdx.x * 128;

    if (tid < 128) tok[tid] = text[by * 128 + tid];
    __syncthreads();

    const int kq = tid & 3;
    const int m0 = tid >> 2;
    const int m1 = m0 + 64;
    const long ar0 = (long)tok[m0] * E;
    const long ar1 = (long)tok[m1] * E;
    const int  g0  = n0 + m0, g1 = n0 + m1;
    const bool vg0 = g0 < G3, vg1 = g1 < G3;

    const int ty = tid >> 4, tx = tid & 15;

    u64 acc[8][4];
    #pragma unroll
    for (int i = 0; i < 8; ++i)
        #pragma unroll
        for (int j = 0; j < 4; ++j) acc[i][j] = 0ULL;

    const float4 z4 = make_float4(0.f, 0.f, 0.f, 0.f);
    float4 aV0, aV1, bV0, bV1;

    {
        const int kk = kq * 4;
        aV0 = *(const float4*)&emb[ar0 + kk];
        aV1 = *(const float4*)&emb[ar1 + kk];
        bV0 = vg0 ? *(const float4*)&wih[(size_t)g0 * E + kk] : z4;
        bV1 = vg1 ? *(const float4*)&wih[(size_t)g1 * E + kk] : z4;
    }

    const int NT = (E + KT - 1) / KT;    // 19
    for (int t = 0; t < NT; ++t) {
        __syncthreads();
        As[kq*4+0][m0] = aV0.x; As[kq*4+1][m0] = aV0.y;
        As[kq*4+2][m0] = aV0.z; As[kq*4+3][m0] = aV0.w;
        As[kq*4+0][m1] = aV1.x; As[kq*4+1][m1] = aV1.y;
        As[kq*4+2][m1] = aV1.z; As[kq*4+3][m1] = aV1.w;
        Bs[kq*4+0][m0] = bV0.x; Bs[kq*4+1][m0] = bV0.y;
        Bs[kq*4+2][m0] = bV0.z; Bs[kq*4+3][m0] = bV0.w;
        Bs[kq*4+0][m1] = bV1.x; Bs[kq*4+1][m1] = bV1.y;
        Bs[kq*4+2][m1] = bV1.z; Bs[kq*4+3][m1] = bV1.w;
        __syncthreads();

        if (t + 1 < NT) {
            const int kk = (t + 1) * KT + kq * 4;
            const bool vk = kk < E;
            aV0 = vk ? *(const float4*)&emb[ar0 + kk] : z4;
            aV1 = vk ? *(const float4*)&emb[ar1 + kk] : z4;
            bV0 = (vk && vg0) ? *(const float4*)&wih[(size_t)g0 * E + kk] : z4;
            bV1 = (vk && vg1) ? *(const float4*)&wih[(size_t)g1 * E + kk] : z4;
        }

        #pragma unroll
        for (int k = 0; k < KT; ++k) {
            float4 a0 = *(const float4*)&As[k][ty * 8];
            float4 a1 = *(const float4*)&As[k][ty * 8 + 4];
            float4 b0 = *(const float4*)&Bs[k][tx * 8];
            float4 b1 = *(const float4*)&Bs[k][tx * 8 + 4];
            u64 bp[4] = { pack2(b0.x, b0.y), pack2(b0.z, b0.w),
                          pack2(b1.x, b1.y), pack2(b1.z, b1.w) };
            float av[8] = { a0.x, a0.y, a0.z, a0.w, a1.x, a1.y, a1.z, a1.w };
            #pragma unroll
            for (int i = 0; i < 8; ++i) {
                u64 ap = pack2(av[i], av[i]);
                #pragma unroll
                for (int j = 0; j < 4; ++j) ffma2(acc[i][j], ap, bp[j]);
            }
        }
    }

    float* gout = g_gi + (size_t)d * ROWS * G3;
    #pragma unroll
    for (int i = 0; i < 8; ++i) {
        const int row = by * 128 + ty * 8 + i;
        float o[8];
        #pragma unroll
        for (int j = 0; j < 4; ++j) unpack2(acc[i][j], o[2*j], o[2*j+1]);
        #pragma unroll
        for (int j = 0; j < 8; ++j) {
            const int g = n0 + tx * 8 + j;
            if (g < G3)
                gout[(size_t)row * G3 + g] = o[j] + bih[g];
        }
    }
}

// ---------------- GRU recurrence: 3-CTA cluster, register-resident weights --
// rank r owns gate slice g in [r*200, r*200+200).
// Thread map (matvec, tid<500): kc = tid/100 (5 chunks of 40 k), gp = tid%100
//   (g-pair). Weights: 40 pre-packed f32x2 (g0,g1) in registers.
// Mail: per step each CTA pushes its 200 (gh+b) values packed (b0,b1) to peers.
#define MAILSTR 608
__global__ void __launch_bounds__(512, 1) __cluster_dims__(3, 1, 1)
gru_rec4(const float* __restrict__ bhh_f, const float* __restrict__ bhh_b,
         const float* __restrict__ h0_f,  const float* __restrict__ h0_b) {
    __shared__ ulonglong2 hsdI[H];       // per k: ((hb0,hb0),(hb1,hb1))
    __shared__ u64  redA[500];           // [kc][gp] partial, batch0 (g0,g1)
    __shared__ u64  redB[500];           // batch1
    __shared__ u64  mail[2 * MAILSTR];   // [buf][g] (b0,b1)
    __shared__ float bo[GS];             // b_hh slice

    const int tid = threadIdx.x;
    const uint32_t rank = ctarank();
    const int group = blockIdx.x / 3;
    const int d  = group >> 4;
    const int b0 = (group & 15) * 2, b1 = b0 + 1;

    const float* bhh = d ? bhh_b : bhh_f;
    const float* h0  = d ? h0_b  : h0_f;

    // ---- load weights into registers (pre-packed g-pairs) ----
    const float* wgd = g_wt + (size_t)d * (H * G3);
    const int kc = tid / 100, gp = tid % 100;
    const bool mv = tid < 500;
    u64 wreg[40];
    if (mv) {
        #pragma unroll
        for (int kk = 0; kk < 40; ++kk)
            wreg[kk] = *(const u64*)(wgd + (size_t)(kc * 40 + kk) * G3
                                     + rank * GS + gp * 2);
    }
    if (tid < GS) {
        bo[tid] = bhh[rank * GS + tid];
        float a = (h0[b0 * H + tid] - 0.5f) * (1.0f / H);
        float c = (h0[b1 * H + tid] - 0.5f) * (1.0f / H);
        hsdI[tid] = make_ulonglong2(pack2(a, a), pack2(c, c));
    }
    __syncthreads();
    CLUSTER_SYNC();                      // peers resident before first push

    const size_t gbase0 = ((size_t)d * ROWS + (size_t)b0 * S) * G3;
    const size_t gbase1 = ((size_t)d * ROWS + (size_t)b1 * S) * G3;
    float* hid0 = g_hid + ((size_t)d * ROWS + (size_t)b0 * S) * H;
    float* hid1 = g_hid + ((size_t)d * ROWS + (size_t)b1 * S) * H;

    const int gj = tid % 200;            // gate-stage j
    const int gb = tid / 200;            // gate-stage batch (tid<400)
    const uint32_t mail_u = s2u(mail);
    const uint32_t pA = mapa_u32(mail_u, (rank + 1) % 3);
    const uint32_t pB = mapa_u32(mail_u, (rank + 2) % 3);

    for (int t = 0; t < S; ++t) {
        const int s = d ? (S - 1 - t) : t;

        // gi prefetch (registers; consumed after cluster sync)
        float gir_ = 0.f, giz_ = 0.f, gin_ = 0.f;
        if (tid < 400) {
            const float* gpt = g_gi + (gb ? gbase1 : gbase0) + (size_t)s * G3 + gj;
            gir_ = gpt[0]; giz_ = gpt[H]; gin_ = gpt[2 * H];
        }

        // matvec from register weights, broadcast LDS of h
        if (mv) {
            u64 accA = 0, accB = 0;
            const ulonglong2* hp = hsdI + kc * 40;
            #pragma unroll
            for (int kk = 0; kk < 40; ++kk) {
                ulonglong2 h2 = hp[kk];
                ffma2(accA, wreg[kk], h2.x);
                ffma2(accB, wreg[kk], h2.y);
            }
            redA[tid] = accA;
            redB[tid] = accB;
        }
        __syncthreads();

        const int mb = (t & 1) * MAILSTR;
        if (tid < 100) {
            u64 sA = redA[tid], sB = redB[tid];
            #pragma unroll
            for (int q = 1; q < 5; ++q) {
                add2(sA, redA[q * 100 + tid]);
                add2(sB, redB[q * 100 + tid]);
            }
            float a0, a1, c0, c1;
            unpack2(sA, a0, a1); unpack2(sB, c0, c1);
            const float bb0 = bo[tid * 2], bb1 = bo[tid * 2 + 1];
            const u64 m0 = pack2(a0 + bb0, c0 + bb0);
            const u64 m1 = pack2(a1 + bb1, c1 + bb1);
            const int g = rank * GS + tid * 2;
            *(ulonglong2*)&mail[mb + g] = make_ulonglong2(m0, m1);
            const uint32_t off = (uint32_t)(mb + g) * 8u;
            stc64(pA + off,     m0);
            stc64(pA + off + 8, m1);
            stc64(pB + off,     m0);
            stc64(pB + off + 8, m1);
        }
        CLUSTER_SYNC();   // arrive=release: all pushes visible cluster-wide

        if (tid < 400) {
            float x, y;
            unpack2(mail[mb + gj],         x, y); const float hr = gb ? y : x;
            unpack2(mail[mb + H + gj],     x, y); const float hz = gb ? y : x;
            unpack2(mail[mb + 2 * H + gj], x, y); const float hn = gb ? y : x;
            float ho, dum;
            unpack2(((const u64*)&hsdI[gj])[gb], ho, dum);
            const float r = 1.f / (1.f + __expf(-(gir_ + hr)));
            const float z = 1.f / (1.f + __expf(-(giz_ + hz)));
            const float n = tanhf(gin_ + r * hn);
            const float hv = (1.f - z) * n + z * ho;
            ((u64*)&hsdI[gj])[gb] = pack2(hv, hv);
            if (rank == 0)
                (gb ? hid1 : hid0)[(size_t)s * H + gj] = hv;
        }
        __syncthreads();
    }
}

// ---------------- final linear: warp per (b,s) row ----------
__global__ void preds_kernel(const float* __restrict__ lin_w,
                             const float* __restrict__ lin_b,
                             float* __restrict__ out) {
    __shared__ float lw[LBL * 2 * H];
    __shared__ float lb[LBL];
    const int tid = threadIdx.x;
    for (int i = tid; i < LBL * 2 * H; i += 256) lw[i] = lin_w[i];
    if (tid < LBL) lb[tid] = lin_b[tid];
    __syncthreads();

    const int wid = tid >> 5, lane = tid & 31;
    const int row = blockIdx.x * 8 + wid;
    const float* hf = g_hid + (size_t)row * H;
    const float* hb = g_hid + (size_t)(ROWS + row) * H;

    float acc[LBL] = {};
    for (int k = lane; k < 2 * H; k += 32) {
        float x = (k < H) ? hf[k] : hb[k - H];
        #pragma unroll
        for (int l = 0; l < LBL; ++l) acc[l] += x * lw[l * 2 * H + k];
    }
    #pragma unroll
    for (int l = 0; l < LBL; ++l) {
        float v = acc[l];
        #pragma unroll
        for (int o = 16; o > 0; o >>= 1) v += __shfl_xor_sync(0xffffffffu, v, o);
        if (lane == 0) out[(size_t)row * LBL + l] = v + lb[l];
    }
}

// ---------------- launch ----------
extern "C" void kernel_launch(void* const* d_in, const int* in_sizes, int n_in,
                              void* d_out, int out_size) {
    const int*   text  = (const int*)  d_in[0];
    const float* emb   = (const float*)d_in[1];
    const float* wih_f = (const float*)d_in[2];
    const float* whh_f = (const float*)d_in[3];
    const float* bih_f = (const float*)d_in[4];
    const float* bhh_f = (const float*)d_in[5];
    const float* wih_b = (const float*)d_in[6];
    const float* whh_b = (const float*)d_in[7];
    const float* bih_b = (const float*)d_in[8];
    const float* bhh_b = (const float*)d_in[9];
    const float* lin_w = (const float*)d_in[10];
    const float* lin_b = (const float*)d_in[11];
    const float* h0_f  = (const float*)d_in[12];
    const float* h0_b  = (const float*)d_in[13];
    float* out = (float*)d_out;

    prep_transpose<<<(G3 * H + 255) / 256, 256>>>(whh_f, whh_b);

    dim3 gg((G3 + 127) / 128, ROWS / 128, 2);   // (5, 128, 2)
    gi_gemm2<<<gg, 256>>>(text, emb, wih_f, bih_f, wih_b, bih_b);

    gru_rec4<<<96, 512>>>(bhh_f, bhh_b, h0_f, h0_b);

    preds_kernel<<<ROWS / 8, 256>>>(lin_w, lin_b, out);
}

// round 5
// speedup vs baseline: 2.0609x; 1.0525x over previous
#include <cuda_runtime.h>
#include <cstddef>
#include <cstdint>

#define B   32
#define S   512
#define E   300
#define H   200
#define G3  600          // 3*H gate rows
#define GS  200          // gate slice per cluster CTA
#define LBL 10
#define ROWS (B*S)       // 16384

#define KT   16
#define PADW 132

typedef unsigned long long u64;

// ---------------- scratch (device globals: no allocations allowed) ----------
__device__ float g_gi [2u*ROWS*(size_t)G3];   // [dir][b*S+s][g]  ~78.6 MB
__device__ float g_wt [2*H*G3];               // w_hh transposed: [dir][k][g]
__device__ float g_hid[2u*ROWS*(size_t)H];    // hidden outputs   ~26.2 MB

// ---------------- f32x2 packed helpers ----------
__device__ __forceinline__ u64 pack2(float x, float y) {
    u64 r; asm("mov.b64 %0, {%1,%2};" : "=l"(r) : "f"(x), "f"(y)); return r;
}
__device__ __forceinline__ void unpack2(u64 v, float& x, float& y) {
    asm("mov.b64 {%0,%1}, %2;" : "=f"(x), "=f"(y) : "l"(v));
}
__device__ __forceinline__ void ffma2(u64& d, u64 a, u64 b) {
    asm("fma.rn.f32x2 %0, %1, %2, %0;" : "+l"(d) : "l"(a), "l"(b));
}
__device__ __forceinline__ void add2(u64& d, u64 a) {
    asm("add.rn.f32x2 %0, %0, %1;" : "+l"(d) : "l"(a));
}

// ---------------- cluster / DSMEM / mbarrier helpers ----------
__device__ __forceinline__ uint32_t s2u(const void* p) {
    uint32_t a;
    asm("{ .reg .u64 t; cvta.to.shared.u64 t, %1; cvt.u32.u64 %0, t; }"
        : "=r"(a) : "l"(p));
    return a;
}
__device__ __forceinline__ uint32_t mapa_u32(uint32_t a, uint32_t r) {
    uint32_t o;
    asm("mapa.shared::cluster.u32 %0, %1, %2;" : "=r"(o) : "r"(a), "r"(r));
    return o;
}
__device__ __forceinline__ uint32_t ctarank() {
    uint32_t r; asm("mov.u32 %0, %%cluster_ctarank;" : "=r"(r)); return r;
}
// async store + remote tx accounting (data + signal in one op)
__device__ __forceinline__ void st_async64(uint32_t raddr, u64 v, uint32_t rmbar) {
    asm volatile(
        "st.async.shared::cluster.mbarrier::complete_tx::bytes.b64 [%0], %1, [%2];"
        :: "r"(raddr), "l"(v), "r"(rmbar) : "memory");
}
__device__ __forceinline__ void mbar_init(uint32_t a, uint32_t cnt) {
    asm volatile("mbarrier.init.shared.b64 [%0], %1;" :: "r"(a), "r"(cnt) : "memory");
}
__device__ __forceinline__ void mbar_arrive_expect_tx(uint32_t a, uint32_t bytes) {
    asm volatile("mbarrier.arrive.expect_tx.shared.b64 _, [%0], %1;"
                 :: "r"(a), "r"(bytes) : "memory");
}
__device__ __forceinline__ void mbar_wait(uint32_t a, uint32_t parity) {
    uint32_t done;
    asm volatile(
        "{\n\t.reg .pred p;\n\t"
        "mbarrier.try_wait.parity.acquire.cta.shared::cta.b64 p, [%1], %2;\n\t"
        "selp.b32 %0, 1, 0, p;\n\t}"
        : "=r"(done) : "r"(a), "r"(parity) : "memory");
    if (!done) {
        asm volatile(
            "{\n\t.reg .pred P1;\n\t"
            "WL_%=:\n\t"
            "mbarrier.try_wait.parity.acquire.cta.shared::cta.b64 P1, [%0], %1, 0x989680;\n\t"
            "@P1 bra.uni WD_%=;\n\t"
            "bra.uni WL_%=;\n\t"
            "WD_%=:\n\t}"
            :: "r"(a), "r"(parity) : "memory");
    }
}
#define CLUSTER_SYNC() do { \
    asm volatile("barrier.cluster.arrive.aligned;" ::: "memory"); \
    asm volatile("barrier.cluster.wait.aligned;" ::: "memory");   \
} while (0)

// ---------------- prep: transpose w_hh into [k][g] ----------
__global__ void prep_transpose(const float* __restrict__ wf,
                               const float* __restrict__ wb) {
    int i = blockIdx.x * blockDim.x + threadIdx.x;
    if (i < G3 * H) {
        int g = i / H, k = i - g * H;
        g_wt[k * G3 + g]          = wf[i];
        g_wt[H * G3 + k * G3 + g] = wb[i];
    }
}

// ---------------- gi = emb[text] @ w_ih^T + b_ih  (128x128 FFMA2 tiles) ----
__global__ void __launch_bounds__(256)
gi_gemm2(const int*   __restrict__ text,
         const float* __restrict__ emb,
         const float* __restrict__ wih_f,
         const float* __restrict__ bih_f,
         const float* __restrict__ wih_b,
         const float* __restrict__ bih_b) {
    const int d = blockIdx.z;
    const float* __restrict__ wih = d ? wih_b : wih_f;
    const float* __restrict__ bih = d ? bih_b : bih_f;

    __shared__ float As[KT][PADW];   // [k][m]
    __shared__ float Bs[KT][PADW];   // [k][n]
    __shared__ int   tok[128];

    const int tid = threadIdx.x;
    const int by  = blockIdx.y;
    const int n0  = blockIdx.x * 128;

    if (tid < 128) tok[tid] = text[by * 128 + tid];
    __syncthreads();

    const int kq = tid & 3;
    const int m0 = tid >> 2;
    const int m1 = m0 + 64;
    const long ar0 = (long)tok[m0] * E;
    const long ar1 = (long)tok[m1] * E;
    const int  g0  = n0 + m0, g1 = n0 + m1;
    const bool vg0 = g0 < G3, vg1 = g1 < G3;

    const int ty = tid >> 4, tx = tid & 15;

    u64 acc[8][4];
    #pragma unroll
    for (int i = 0; i < 8; ++i)
        #pragma unroll
        for (int j = 0; j < 4; ++j) acc[i][j] = 0ULL;

    const float4 z4 = make_float4(0.f, 0.f, 0.f, 0.f);
    float4 aV0, aV1, bV0, bV1;

    {
        const int kk = kq * 4;
        aV0 = *(const float4*)&emb[ar0 + kk];
        aV1 = *(const float4*)&emb[ar1 + kk];
        bV0 = vg0 ? *(const float4*)&wih[(size_t)g0 * E + kk] : z4;
        bV1 = vg1 ? *(const float4*)&wih[(size_t)g1 * E + kk] : z4;
    }

    const int NT = (E + KT - 1) / KT;    // 19
    for (int t = 0; t < NT; ++t) {
        __syncthreads();
        As[kq*4+0][m0] = aV0.x; As[kq*4+1][m0] = aV0.y;
        As[kq*4+2][m0] = aV0.z; As[kq*4+3][m0] = aV0.w;
        As[kq*4+0][m1] = aV1.x; As[kq*4+1][m1] = aV1.y;
        As[kq*4+2][m1] = aV1.z; As[kq*4+3][m1] = aV1.w;
        Bs[kq*4+0][m0] = bV0.x; Bs[kq*4+1][m0] = bV0.y;
        Bs[kq*4+2][m0] = bV0.z; Bs[kq*4+3][m0] = bV0.w;
        Bs[kq*4+0][m1] = bV1.x; Bs[kq*4+1][m1] = bV1.y;
        Bs[kq*4+2][m1] = bV1.z; Bs[kq*4+3][m1] = bV1.w;
        __syncthreads();

        if (t + 1 < NT) {
            const int kk = (t + 1) * KT + kq * 4;
            const bool vk = kk < E;
            aV0 = vk ? *(const float4*)&emb[ar0 + kk] : z4;
            aV1 = vk ? *(const float4*)&emb[ar1 + kk] : z4;
            bV0 = (vk && vg0) ? *(const float4*)&wih[(size_t)g0 * E + kk] : z4;
            bV1 = (vk && vg1) ? *(const float4*)&wih[(size_t)g1 * E + kk] : z4;
        }

        #pragma unroll
        for (int k = 0; k < KT; ++k) {
            float4 a0 = *(const float4*)&As[k][ty * 8];
            float4 a1 = *(const float4*)&As[k][ty * 8 + 4];
            float4 b0 = *(const float4*)&Bs[k][tx * 8];
            float4 b1 = *(const float4*)&Bs[k][tx * 8 + 4];
            u64 bp[4] = { pack2(b0.x, b0.y), pack2(b0.z, b0.w),
                          pack2(b1.x, b1.y), pack2(b1.z, b1.w) };
            float av[8] = { a0.x, a0.y, a0.z, a0.w, a1.x, a1.y, a1.z, a1.w };
            #pragma unroll
            for (int i = 0; i < 8; ++i) {
                u64 ap = pack2(av[i], av[i]);
                #pragma unroll
                for (int j = 0; j < 4; ++j) ffma2(acc[i][j], ap, bp[j]);
            }
        }
    }

    float* gout = g_gi + (size_t)d * ROWS * G3;
    #pragma unroll
    for (int i = 0; i < 8; ++i) {
        const int row = by * 128 + ty * 8 + i;
        float o[8];
        #pragma unroll
        for (int j = 0; j < 4; ++j) unpack2(acc[i][j], o[2*j], o[2*j+1]);
        #pragma unroll
        for (int j = 0; j < 8; ++j) {
            const int g = n0 + tx * 8 + j;
            if (g < G3)
                gout[(size_t)row * G3 + g] = o[j] + bih[g];
        }
    }
}

// ---------------- GRU recurrence: 3-CTA cluster, mbarrier st.async protocol -
// rank r owns gate slice g in [r*200, r*200+200).
// Per step: matvec (500 thr, reg weights) -> bar -> reduce+st.async push
// (100 thr, data+tx to all 3 CTAs) -> mbar acquire wait -> gates (400 thr).
#define MAILW 608
#define TXBYTES (G3 * 8)        // 4800: 600 u64 (b0,b1) per step per CTA
__global__ void __launch_bounds__(512, 1) __cluster_dims__(3, 1, 1)
gru_rec5(const float* __restrict__ bhh_f, const float* __restrict__ bhh_b,
         const float* __restrict__ h0_f,  const float* __restrict__ h0_b) {
    __shared__ ulonglong2 hsdI[H];       // per k: ((hb0,hb0),(hb1,hb1))
    __shared__ u64  redA[500];           // [kc][gp] partial, batch0 (g0,g1)
    __shared__ u64  redB[500];           // batch1
    __shared__ u64  mail[2 * MAILW];     // [buf][g] (b0,b1)
    __shared__ float bo[GS];             // b_hh slice
    __shared__ __align__(8) u64 mbar[2];

    const int tid = threadIdx.x;
    const uint32_t rank = ctarank();
    const int group = blockIdx.x / 3;
    const int d  = group >> 4;
    const int b0 = (group & 15) * 2, b1 = b0 + 1;

    const float* bhh = d ? bhh_b : bhh_f;
    const float* h0  = d ? h0_b  : h0_f;

    // ---- load weights into registers (pre-packed g-pairs) ----
    const float* wgd = g_wt + (size_t)d * (H * G3);
    const int kc = tid / 100, gp = tid % 100;
    const bool mv = tid < 500;
    u64 wreg[40];
    if (mv) {
        #pragma unroll
        for (int kk = 0; kk < 40; ++kk)
            wreg[kk] = *(const u64*)(wgd + (size_t)(kc * 40 + kk) * G3
                                     + rank * GS + gp * 2);
    }
    if (tid < GS) {
        bo[tid] = bhh[rank * GS + tid];
        float a = (h0[b0 * H + tid] - 0.5f) * (1.0f / H);
        float c = (h0[b1 * H + tid] - 0.5f) * (1.0f / H);
        hsdI[tid] = make_ulonglong2(pack2(a, a), pack2(c, c));
    }
    const uint32_t mbar_u = s2u(mbar);
    if (tid == 0) {
        mbar_init(mbar_u, 1);
        mbar_init(mbar_u + 8, 1);
        mbar_arrive_expect_tx(mbar_u,     TXBYTES);   // arm for t=0
        mbar_arrive_expect_tx(mbar_u + 8, TXBYTES);   // arm for t=1
    }
    __syncthreads();
    CLUSTER_SYNC();        // peers' mbarriers armed before any st.async

    const size_t gbase0 = ((size_t)d * ROWS + (size_t)b0 * S) * G3;
    const size_t gbase1 = ((size_t)d * ROWS + (size_t)b1 * S) * G3;
    float* hid0 = g_hid + ((size_t)d * ROWS + (size_t)b0 * S) * H;
    float* hid1 = g_hid + ((size_t)d * ROWS + (size_t)b1 * S) * H;

    const int gj = tid % 200;            // gate-stage j
    const int gb = tid / 200;            // gate-stage batch (tid<400)
    const uint32_t mail_u = s2u(mail);
    // per-destination-rank bases for mail and mbar (cluster window)
    const uint32_t mailR[3] = { mapa_u32(mail_u, 0), mapa_u32(mail_u, 1),
                                mapa_u32(mail_u, 2) };
    const uint32_t mbarR[3] = { mapa_u32(mbar_u, 0), mapa_u32(mbar_u, 1),
                                mapa_u32(mbar_u, 2) };

    for (int t = 0; t < S; ++t) {
        const int s = d ? (S - 1 - t) : t;
        const int buf = t & 1;

        // gi prefetch (registers; consumed in gate stage)
        float gir_ = 0.f, giz_ = 0.f, gin_ = 0.f;
        if (tid < 400) {
            const float* gpt = g_gi + (gb ? gbase1 : gbase0) + (size_t)s * G3 + gj;
            gir_ = gpt[0]; giz_ = gpt[H]; gin_ = gpt[2 * H];
        }

        // matvec from register weights, broadcast LDS of h
        if (mv) {
            u64 accA = 0, accB = 0;
            const ulonglong2* hp = hsdI + kc * 40;
            #pragma unroll
            for (int kk = 0; kk < 40; ++kk) {
                ulonglong2 h2 = hp[kk];
                ffma2(accA, wreg[kk], h2.x);
                ffma2(accB, wreg[kk], h2.y);
            }
            redA[tid] = accA;
            redB[tid] = accB;
        }
        __syncthreads();

        if (tid < 100) {
            u64 sA = redA[tid], sB = redB[tid];
            #pragma unroll
            for (int q = 1; q < 5; ++q) {
                add2(sA, redA[q * 100 + tid]);
                add2(sB, redB[q * 100 + tid]);
            }
            float a0, a1, c0, c1;
            unpack2(sA, a0, a1); unpack2(sB, c0, c1);
            const float bb0 = bo[tid * 2], bb1 = bo[tid * 2 + 1];
            const u64 m0 = pack2(a0 + bb0, c0 + bb0);
            const u64 m1 = pack2(a1 + bb1, c1 + bb1);
            const uint32_t off = (uint32_t)(buf * MAILW + rank * GS + tid * 2) * 8u;
            const uint32_t mboff = (uint32_t)buf * 8u;
            #pragma unroll
            for (int rr = 0; rr < 3; ++rr) {
                st_async64(mailR[rr] + off,     m0, mbarR[rr] + mboff);
                st_async64(mailR[rr] + off + 8, m1, mbarR[rr] + mboff);
            }
        }

        // wait for all 4800 bytes (own + 2 peers) to land
        mbar_wait(mbar_u + buf * 8, (t >> 1) & 1);
        if (tid == 0 && t + 2 < S)
            mbar_arrive_expect_tx(mbar_u + buf * 8, TXBYTES);  // re-arm t+2

        if (tid < 400) {
            const u64* mb_ = mail + buf * MAILW;
            float x, y;
            unpack2(mb_[gj],         x, y); const float hr = gb ? y : x;
            unpack2(mb_[H + gj],     x, y); const float hz = gb ? y : x;
            unpack2(mb_[2 * H + gj], x, y); const float hn = gb ? y : x;
            float ho, dum;
            unpack2(((const u64*)&hsdI[gj])[gb], ho, dum);
            const float r = 1.f / (1.f + __expf(-(gir_ + hr)));
            const float z = 1.f / (1.f + __expf(-(giz_ + hz)));
            float xt = gin_ + r * hn;
            xt = fminf(fmaxf(xt, -30.f), 30.f);
            const float e = __expf(-2.f * xt);
            const float n = (1.f - e) / (1.f + e);
            const float hv = (1.f - z) * n + z * ho;
            ((u64*)&hsdI[gj])[gb] = pack2(hv, hv);
            if (rank == 0)
                (gb ? hid1 : hid0)[(size_t)s * H + gj] = hv;
        }
        __syncthreads();
    }
}

// ---------------- final linear: warp per (b,s) row ----------
__global__ void preds_kernel(const float* __restrict__ lin_w,
                             const float* __restrict__ lin_b,
                             float* __restrict__ out) {
    __shared__ float lw[LBL * 2 * H];
    __shared__ float lb[LBL];
    const int tid = threadIdx.x;
    for (int i = tid; i < LBL * 2 * H; i += 256) lw[i] = lin_w[i];
    if (tid < LBL) lb[tid] = lin_b[tid];
    __syncthreads();

    const int wid = tid >> 5, lane = tid & 31;
    const int row = blockIdx.x * 8 + wid;
    const float* hf = g_hid + (size_t)row * H;
    const float* hb = g_hid + (size_t)(ROWS + row) * H;

    float acc[LBL] = {};
    for (int k = lane; k < 2 * H; k += 32) {
        float x = (k < H) ? hf[k] : hb[k - H];
        #pragma unroll
        for (int l = 0; l < LBL; ++l) acc[l] += x * lw[l * 2 * H + k];
    }
    #pragma unroll
    for (int l = 0; l < LBL; ++l) {
        float v = acc[l];
        #pragma unroll
        for (int o = 16; o > 0; o >>= 1) v += __shfl_xor_sync(0xffffffffu, v, o);
        if (lane == 0) out[(size_t)row * LBL + l] = v + lb[l];
    }
}

// ---------------- launch ----------
extern "C" void kernel_launch(void* const* d_in, const int* in_sizes, int n_in,
                              void* d_out, int out_size) {
    const int*   text  = (const int*)  d_in[0];
    const float* emb   = (const float*)d_in[1];
    const float* wih_f = (const float*)d_in[2];
    const float* whh_f = (const float*)d_in[3];
    const float* bih_f = (const float*)d_in[4];
    const float* bhh_f = (const float*)d_in[5];
    const float* wih_b = (const float*)d_in[6];
    const float* whh_b = (const float*)d_in[7];
    const float* bih_b = (const float*)d_in[8];
    const float* bhh_b = (const float*)d_in[9];
    const float* lin_w = (const float*)d_in[10];
    const float* lin_b = (const float*)d_in[11];
    const float* h0_f  = (const float*)d_in[12];
    const float* h0_b  = (const float*)d_in[13];
    float* out = (float*)d_out;

    prep_transpose<<<(G3 * H + 255) / 256, 256>>>(whh_f, whh_b);

    dim3 gg((G3 + 127) / 128, ROWS / 128, 2);   // (5, 128, 2)
    gi_gemm2<<<gg, 256>>>(text, emb, wih_f, bih_f, wih_b, bih_b);

    gru_rec5<<<96, 512>>>(bhh_f, bhh_b, h0_f, h0_b);

    preds_kernel<<<ROWS / 8, 256>>>(lin_w, lin_b, out);
}

// round 6
// speedup vs baseline: 2.4319x; 1.1800x over previous
#include <cuda_runtime.h>
#include <cstddef>
#include <cstdint>

#define B   32
#define S   512
#define E   300
#define H   200
#define G3  600          // 3*H gate rows
#define GS  200          // gate slice per cluster CTA
#define LBL 10
#define ROWS (B*S)       // 16384

#define KT   16
#define PADW 132

typedef unsigned long long u64;

// ---------------- scratch (device globals: no allocations allowed) ----------
__device__ float g_gi [2u*ROWS*(size_t)G3];   // [dir][b*S+s][g]  ~78.6 MB
__device__ float g_wt [2*H*G3];               // w_hh transposed: [dir][k][g]
__device__ float g_hid[2u*ROWS*(size_t)H];    // hidden outputs   ~26.2 MB

// ---------------- f32x2 packed helpers ----------
__device__ __forceinline__ u64 pack2(float x, float y) {
    u64 r; asm("mov.b64 %0, {%1,%2};" : "=l"(r) : "f"(x), "f"(y)); return r;
}
__device__ __forceinline__ void unpack2(u64 v, float& x, float& y) {
    asm("mov.b64 {%0,%1}, %2;" : "=f"(x), "=f"(y) : "l"(v));
}
__device__ __forceinline__ void ffma2(u64& d, u64 a, u64 b) {
    asm("fma.rn.f32x2 %0, %1, %2, %0;" : "+l"(d) : "l"(a), "l"(b));
}
__device__ __forceinline__ void add2(u64& d, u64 a) {
    asm("add.rn.f32x2 %0, %0, %1;" : "+l"(d) : "l"(a));
}

// ---------------- cluster / DSMEM / mbarrier helpers ----------
__device__ __forceinline__ uint32_t s2u(const void* p) {
    uint32_t a;
    asm("{ .reg .u64 t; cvta.to.shared.u64 t, %1; cvt.u32.u64 %0, t; }"
        : "=r"(a) : "l"(p));
    return a;
}
__device__ __forceinline__ uint32_t mapa_u32(uint32_t a, uint32_t r) {
    uint32_t o;
    asm("mapa.shared::cluster.u32 %0, %1, %2;" : "=r"(o) : "r"(a), "r"(r));
    return o;
}
__device__ __forceinline__ uint32_t ctarank() {
    uint32_t r; asm("mov.u32 %0, %%cluster_ctarank;" : "=r"(r)); return r;
}
__device__ __forceinline__ void st_async64(uint32_t raddr, u64 v, uint32_t rmbar) {
    asm volatile(
        "st.async.shared::cluster.mbarrier::complete_tx::bytes.b64 [%0], %1, [%2];"
        :: "r"(raddr), "l"(v), "r"(rmbar) : "memory");
}
__device__ __forceinline__ void mbar_init(uint32_t a, uint32_t cnt) {
    asm volatile("mbarrier.init.shared.b64 [%0], %1;" :: "r"(a), "r"(cnt) : "memory");
}
__device__ __forceinline__ void mbar_arrive_expect_tx(uint32_t a, uint32_t bytes) {
    asm volatile("mbarrier.arrive.expect_tx.shared.b64 _, [%0], %1;"
                 :: "r"(a), "r"(bytes) : "memory");
}
__device__ __forceinline__ void mbar_wait(uint32_t a, uint32_t parity) {
    uint32_t done;
    asm volatile(
        "{\n\t.reg .pred p;\n\t"
        "mbarrier.try_wait.parity.acquire.cta.shared::cta.b64 p, [%1], %2;\n\t"
        "selp.b32 %0, 1, 0, p;\n\t}"
        : "=r"(done) : "r"(a), "r"(parity) : "memory");
    if (!done) {
        asm volatile(
            "{\n\t.reg .pred P1;\n\t"
            "WL_%=:\n\t"
            "mbarrier.try_wait.parity.acquire.cta.shared::cta.b64 P1, [%0], %1, 0x989680;\n\t"
            "@P1 bra.uni WD_%=;\n\t"
            "bra.uni WL_%=;\n\t"
            "WD_%=:\n\t}"
            :: "r"(a), "r"(parity) : "memory");
    }
}
#define CLUSTER_SYNC() do { \
    asm volatile("barrier.cluster.arrive.aligned;" ::: "memory"); \
    asm volatile("barrier.cluster.wait.aligned;" ::: "memory");   \
} while (0)

// ---------------- prep: transpose w_hh into [k][g] ----------
__global__ void prep_transpose(const float* __restrict__ wf,
                               const float* __restrict__ wb) {
    int i = blockIdx.x * blockDim.x + threadIdx.x;
    if (i < G3 * H) {
        int g = i / H, k = i - g * H;
        g_wt[k * G3 + g]          = wf[i];
        g_wt[H * G3 + k * G3 + g] = wb[i];
    }
}

// ---------------- gi = emb[text] @ w_ih^T + b_ih  (128x128 FFMA2 tiles) ----
__global__ void __launch_bounds__(256)
gi_gemm2(const int*   __restrict__ text,
         const float* __restrict__ emb,
         const float* __restrict__ wih_f,
         const float* __restrict__ bih_f,
         const float* __restrict__ wih_b,
         const float* __restrict__ bih_b) {
    const int d = blockIdx.z;
    const float* __restrict__ wih = d ? wih_b : wih_f;
    const float* __restrict__ bih = d ? bih_b : bih_f;

    __shared__ float As[KT][PADW];   // [k][m]
    __shared__ float Bs[KT][PADW];   // [k][n]
    __shared__ int   tok[128];

    const int tid = threadIdx.x;
    const int by  = blockIdx.y;
    const int n0  = blockIdx.x * 128;

    if (tid < 128) tok[tid] = text[by * 128 + tid];
    __syncthreads();

    const int kq = tid & 3;
    const int m0 = tid >> 2;
    const int m1 = m0 + 64;
    const long ar0 = (long)tok[m0] * E;
    const long ar1 = (long)tok[m1] * E;
    const int  g0  = n0 + m0, g1 = n0 + m1;
    const bool vg0 = g0 < G3, vg1 = g1 < G3;

    const int ty = tid >> 4, tx = tid & 15;

    u64 acc[8][4];
    #pragma unroll
    for (int i = 0; i < 8; ++i)
        #pragma unroll
        for (int j = 0; j < 4; ++j) acc[i][j] = 0ULL;

    const float4 z4 = make_float4(0.f, 0.f, 0.f, 0.f);
    float4 aV0, aV1, bV0, bV1;

    {
        const int kk = kq * 4;
        aV0 = *(const float4*)&emb[ar0 + kk];
        aV1 = *(const float4*)&emb[ar1 + kk];
        bV0 = vg0 ? *(const float4*)&wih[(size_t)g0 * E + kk] : z4;
        bV1 = vg1 ? *(const float4*)&wih[(size_t)g1 * E + kk] : z4;
    }

    const int NT = (E + KT - 1) / KT;    // 19
    for (int t = 0; t < NT; ++t) {
        __syncthreads();
        As[kq*4+0][m0] = aV0.x; As[kq*4+1][m0] = aV0.y;
        As[kq*4+2][m0] = aV0.z; As[kq*4+3][m0] = aV0.w;
        As[kq*4+0][m1] = aV1.x; As[kq*4+1][m1] = aV1.y;
        As[kq*4+2][m1] = aV1.z; As[kq*4+3][m1] = aV1.w;
        Bs[kq*4+0][m0] = bV0.x; Bs[kq*4+1][m0] = bV0.y;
        Bs[kq*4+2][m0] = bV0.z; Bs[kq*4+3][m0] = bV0.w;
        Bs[kq*4+0][m1] = bV1.x; Bs[kq*4+1][m1] = bV1.y;
        Bs[kq*4+2][m1] = bV1.z; Bs[kq*4+3][m1] = bV1.w;
        __syncthreads();

        if (t + 1 < NT) {
            const int kk = (t + 1) * KT + kq * 4;
            const bool vk = kk < E;
            aV0 = vk ? *(const float4*)&emb[ar0 + kk] : z4;
            aV1 = vk ? *(const float4*)&emb[ar1 + kk] : z4;
            bV0 = (vk && vg0) ? *(const float4*)&wih[(size_t)g0 * E + kk] : z4;
            bV1 = (vk && vg1) ? *(const float4*)&wih[(size_t)g1 * E + kk] : z4;
        }

        #pragma unroll
        for (int k = 0; k < KT; ++k) {
            float4 a0 = *(const float4*)&As[k][ty * 8];
            float4 a1 = *(const float4*)&As[k][ty * 8 + 4];
            float4 b0 = *(const float4*)&Bs[k][tx * 8];
            float4 b1 = *(const float4*)&Bs[k][tx * 8 + 4];
            u64 bp[4] = { pack2(b0.x, b0.y), pack2(b0.z, b0.w),
                          pack2(b1.x, b1.y), pack2(b1.z, b1.w) };
            float av[8] = { a0.x, a0.y, a0.z, a0.w, a1.x, a1.y, a1.z, a1.w };
            #pragma unroll
            for (int i = 0; i < 8; ++i) {
                u64 ap = pack2(av[i], av[i]);
                #pragma unroll
                for (int j = 0; j < 4; ++j) ffma2(acc[i][j], ap, bp[j]);
            }
        }
    }

    float* gout = g_gi + (size_t)d * ROWS * G3;
    #pragma unroll
    for (int i = 0; i < 8; ++i) {
        const int row = by * 128 + ty * 8 + i;
        float o[8];
        #pragma unroll
        for (int j = 0; j < 4; ++j) unpack2(acc[i][j], o[2*j], o[2*j+1]);
        #pragma unroll
        for (int j = 0; j < 8; ++j) {
            const int g = n0 + tx * 8 + j;
            if (g < G3)
                gout[(size_t)row * G3 + g] = o[j] + bih[g];
        }
    }
}

// ---------------- GRU recurrence: 3-CTA cluster, batch-staggered pipeline ---
// rank r owns gate slice g in [r*200, r*200+200).
// Per step: mv(b0)->bar->push(b0) | mv(b1)->bar->push(b1) | wait(b0)->
// gates(b0) | wait(b1)->gates(b1) | bar.  b0's DSMEM flight hides under
// mv(b1); b1's flight hides under gates(b0).
#define MAILW 608                 // floats per (buf,batch) mail slab
#define TXB   (G3 * 4)            // 2400 B per batch per step (600 floats)
__global__ void __launch_bounds__(512, 1) __cluster_dims__(3, 1, 1)
gru_rec6(const float* __restrict__ bhh_f, const float* __restrict__ bhh_b,
         const float* __restrict__ h0_f,  const float* __restrict__ h0_b) {
    __shared__ u64  hsd0[H];             // (h,h) per k, batch 0
    __shared__ u64  hsd1[H];             // batch 1
    __shared__ u64  redA[500];           // matvec partials, batch 0
    __shared__ u64  redB[500];           // batch 1
    __shared__ float mailf[4 * MAILW];   // [buf*2+batch][g]
    __shared__ u64  bo2[100];            // b_hh g-pairs
    __shared__ __align__(8) u64 mbar[4]; // [buf*2+batch]

    const int tid = threadIdx.x;
    const uint32_t rank = ctarank();
    const int group = blockIdx.x / 3;
    const int d  = group >> 4;
    const int b0 = (group & 15) * 2, b1 = b0 + 1;

    const float* bhh = d ? bhh_b : bhh_f;
    const float* h0  = d ? h0_b  : h0_f;

    // ---- weights into registers (pre-packed (g0,g1) pairs) ----
    const float* wgd = g_wt + (size_t)d * (H * G3);
    const int kc = tid / 100, gp = tid % 100;
    const bool mv = tid < 500;
    u64 wreg[40];
    if (mv) {
        #pragma unroll
        for (int kk = 0; kk < 40; ++kk)
            wreg[kk] = *(const u64*)(wgd + (size_t)(kc * 40 + kk) * G3
                                     + rank * GS + gp * 2);
    }
    if (tid < 100)
        bo2[tid] = *(const u64*)(bhh + rank * GS + tid * 2);
    if (tid < H) {
        float a = (h0[b0 * H + tid] - 0.5f) * (1.0f / H);
        float c = (h0[b1 * H + tid] - 0.5f) * (1.0f / H);
        hsd0[tid] = pack2(a, a);
        hsd1[tid] = pack2(c, c);
    }
    const uint32_t mbar_u = s2u(mbar);
    if (tid == 0) {
        #pragma unroll
        for (int i = 0; i < 4; ++i) {
            mbar_init(mbar_u + i * 8, 1);
            mbar_arrive_expect_tx(mbar_u + i * 8, TXB);   // arm t=0 and t=1
        }
    }
    __syncthreads();
    CLUSTER_SYNC();        // peers' mbarriers armed before any st.async

    const size_t gbase0 = ((size_t)d * ROWS + (size_t)b0 * S) * G3;
    const size_t gbase1 = ((size_t)d * ROWS + (size_t)b1 * S) * G3;
    float* hid0 = g_hid + ((size_t)d * ROWS + (size_t)b0 * S) * H;
    float* hid1 = g_hid + ((size_t)d * ROWS + (size_t)b1 * S) * H;

    const uint32_t mail_u = s2u(mailf);
    const uint32_t mailR[3] = { mapa_u32(mail_u, 0), mapa_u32(mail_u, 1),
                                mapa_u32(mail_u, 2) };
    const uint32_t mbarR[3] = { mapa_u32(mbar_u, 0), mapa_u32(mbar_u, 1),
                                mapa_u32(mbar_u, 2) };

    for (int t = 0; t < S; ++t) {
        const int s   = d ? (S - 1 - t) : t;
        const int buf = t & 1;
        const uint32_t par = (t >> 1) & 1;

        // gi prefetch for both batches (registers; consumed in gates)
        float gir0 = 0.f, giz0 = 0.f, gin0 = 0.f;
        float gir1 = 0.f, giz1 = 0.f, gin1 = 0.f;
        if (tid < H) {
            const float* p0 = g_gi + gbase0 + (size_t)s * G3 + tid;
            const float* p1 = g_gi + gbase1 + (size_t)s * G3 + tid;
            gir0 = p0[0]; giz0 = p0[H]; gin0 = p0[2 * H];
            gir1 = p1[0]; giz1 = p1[H]; gin1 = p1[2 * H];
        }

        // ---- matvec b0 ----
        if (mv) {
            u64 acc = 0;
            const u64* hp = hsd0 + kc * 40;
            #pragma unroll
            for (int kk = 0; kk < 40; ++kk) ffma2(acc, wreg[kk], hp[kk]);
            redA[tid] = acc;
        }
        __syncthreads();                               // bar1: redA ready

        if (tid < 100) {                               // reduce + push b0
            u64 sA = redA[tid];
            #pragma unroll
            for (int q = 1; q < 5; ++q) add2(sA, redA[q * 100 + tid]);
            add2(sA, bo2[tid]);
            const uint32_t off = (uint32_t)((buf * 2 + 0) * MAILW
                                            + rank * GS + tid * 2) * 4u;
            const uint32_t mboff = (uint32_t)(buf * 2 + 0) * 8u;
            #pragma unroll
            for (int rr = 0; rr < 3; ++rr)
                st_async64(mailR[rr] + off, sA, mbarR[rr] + mboff);
        }

        // ---- matvec b1 (covers b0's DSMEM flight) ----
        if (mv) {
            u64 acc = 0;
            const u64* hp = hsd1 + kc * 40;
            #pragma unroll
            for (int kk = 0; kk < 40; ++kk) ffma2(acc, wreg[kk], hp[kk]);
            redB[tid] = acc;
        }
        __syncthreads();                               // bar2: redB ready

        if (tid < 100) {                               // reduce + push b1
            u64 sB = redB[tid];
            #pragma unroll
            for (int q = 1; q < 5; ++q) add2(sB, redB[q * 100 + tid]);
            add2(sB, bo2[tid]);
            const uint32_t off = (uint32_t)((buf * 2 + 1) * MAILW
                                            + rank * GS + tid * 2) * 4u;
            const uint32_t mboff = (uint32_t)(buf * 2 + 1) * 8u;
            #pragma unroll
            for (int rr = 0; rr < 3; ++rr)
                st_async64(mailR[rr] + off, sB, mbarR[rr] + mboff);
        }

        // ---- gates b0 ----
        if (tid < H) {
            mbar_wait(mbar_u + (buf * 2 + 0) * 8, par);
            if (tid == 0 && t + 2 < S)
                mbar_arrive_expect_tx(mbar_u + (buf * 2 + 0) * 8, TXB);
            const float* mb_ = mailf + (buf * 2 + 0) * MAILW;
            const float hr = mb_[tid], hz = mb_[H + tid], hn = mb_[2 * H + tid];
            float ho, dum; unpack2(hsd0[tid], ho, dum);
            const float r = 1.f / (1.f + __expf(-(gir0 + hr)));
            const float z = 1.f / (1.f + __expf(-(giz0 + hz)));
            float xt = gin0 + r * hn;
            xt = fminf(fmaxf(xt, -30.f), 30.f);
            const float e = __expf(-2.f * xt);
            const float n = (1.f - e) / (1.f + e);
            const float hv = (1.f - z) * n + z * ho;
            hsd0[tid] = pack2(hv, hv);
            if (rank == 0) hid0[(size_t)s * H + tid] = hv;
        }

        // ---- gates b1 ----
        if (tid < H) {
            mbar_wait(mbar_u + (buf * 2 + 1) * 8, par);
            if (tid == 0 && t + 2 < S)
                mbar_arrive_expect_tx(mbar_u + (buf * 2 + 1) * 8, TXB);
            const float* mb_ = mailf + (buf * 2 + 1) * MAILW;
            const float hr = mb_[tid], hz = mb_[H + tid], hn = mb_[2 * H + tid];
            float ho, dum; unpack2(hsd1[tid], ho, dum);
            const float r = 1.f / (1.f + __expf(-(gir1 + hr)));
            const float z = 1.f / (1.f + __expf(-(giz1 + hz)));
            float xt = gin1 + r * hn;
            xt = fminf(fmaxf(xt, -30.f), 30.f);
            const float e = __expf(-2.f * xt);
            const float n = (1.f - e) / (1.f + e);
            const float hv = (1.f - z) * n + z * ho;
            hsd1[tid] = pack2(hv, hv);
            if (rank == 0) hid1[(size_t)s * H + tid] = hv;
        }
        __syncthreads();                               // bar3: hsd stable
    }
}

// ---------------- final linear: warp per (b,s) row ----------
__global__ void preds_kernel(const float* __restrict__ lin_w,
                             const float* __restrict__ lin_b,
                             float* __restrict__ out) {
    __shared__ float lw[LBL * 2 * H];
    __shared__ float lb[LBL];
    const int tid = threadIdx.x;
    for (int i = tid; i < LBL * 2 * H; i += 256) lw[i] = lin_w[i];
    if (tid < LBL) lb[tid] = lin_b[tid];
    __syncthreads();

    const int wid = tid >> 5, lane = tid & 31;
    const int row = blockIdx.x * 8 + wid;
    const float* hf = g_hid + (size_t)row * H;
    const float* hb = g_hid + (size_t)(ROWS + row) * H;

    float acc[LBL] = {};
    for (int k = lane; k < 2 * H; k += 32) {
        float x = (k < H) ? hf[k] : hb[k - H];
        #pragma unroll
        for (int l = 0; l < LBL; ++l) acc[l] += x * lw[l * 2 * H + k];
    }
    #pragma unroll
    for (int l = 0; l < LBL; ++l) {
        float v = acc[l];
        #pragma unroll
        for (int o = 16; o > 0; o >>= 1) v += __shfl_xor_sync(0xffffffffu, v, o);
        if (lane == 0) out[(size_t)row * LBL + l] = v + lb[l];
    }
}

// ---------------- launch ----------
extern "C" void kernel_launch(void* const* d_in, const int* in_sizes, int n_in,
                              void* d_out, int out_size) {
    const int*   text  = (const int*)  d_in[0];
    const float* emb   = (const float*)d_in[1];
    const float* wih_f = (const float*)d_in[2];
    const float* whh_f = (const float*)d_in[3];
    const float* bih_f = (const float*)d_in[4];
    const float* bhh_f = (const float*)d_in[5];
    const float* wih_b = (const float*)d_in[6];
    const float* whh_b = (const float*)d_in[7];
    const float* bih_b = (const float*)d_in[8];
    const float* bhh_b = (const float*)d_in[9];
    const float* lin_w = (const float*)d_in[10];
    const float* lin_b = (const float*)d_in[11];
    const float* h0_f  = (const float*)d_in[12];
    const float* h0_b  = (const float*)d_in[13];
    float* out = (float*)d_out;

    prep_transpose<<<(G3 * H + 255) / 256, 256>>>(whh_f, whh_b);

    dim3 gg((G3 + 127) / 128, ROWS / 128, 2);   // (5, 128, 2)
    gi_gemm2<<<gg, 256>>>(text, emb, wih_f, bih_f, wih_b, bih_b);

    gru_rec6<<<96, 512>>>(bhh_f, bhh_b, h0_f, h0_b);

    preds_kernel<<<ROWS / 8, 256>>>(lin_w, lin_b, out);
}

// round 7
// speedup vs baseline: 2.7628x; 1.1361x over previous
#include <cuda_runtime.h>
#include <cstddef>
#include <cstdint>

#define B   32
#define S   512
#define E   300
#define H   200
#define G3  600          // 3*H gate rows
#define GS  200          // gate slice per cluster CTA
#define LBL 10
#define ROWS (B*S)       // 16384

#define KT   16
#define PADW 132

typedef unsigned long long u64;

// ---------------- scratch (device globals: no allocations allowed) ----------
__device__ float g_gi [2u*ROWS*(size_t)G3];   // [dir][b*S+s][g]  ~78.6 MB
__device__ float g_wt [2*H*G3];               // w_hh transposed: [dir][k][g]
__device__ float g_hid[2u*ROWS*(size_t)H];    // hidden outputs   ~26.2 MB

// ---------------- f32x2 packed helpers ----------
__device__ __forceinline__ u64 pack2(float x, float y) {
    u64 r; asm("mov.b64 %0, {%1,%2};" : "=l"(r) : "f"(x), "f"(y)); return r;
}
__device__ __forceinline__ void unpack2(u64 v, float& x, float& y) {
    asm("mov.b64 {%0,%1}, %2;" : "=f"(x), "=f"(y) : "l"(v));
}
__device__ __forceinline__ void ffma2(u64& d, u64 a, u64 b) {
    asm("fma.rn.f32x2 %0, %1, %2, %0;" : "+l"(d) : "l"(a), "l"(b));
}
__device__ __forceinline__ void add2(u64& d, u64 a) {
    asm("add.rn.f32x2 %0, %0, %1;" : "+l"(d) : "l"(a));
}

// ---------------- cluster / DSMEM / mbarrier helpers ----------
__device__ __forceinline__ uint32_t s2u(const void* p) {
    uint32_t a;
    asm("{ .reg .u64 t; cvta.to.shared.u64 t, %1; cvt.u32.u64 %0, t; }"
        : "=r"(a) : "l"(p));
    return a;
}
__device__ __forceinline__ uint32_t mapa_u32(uint32_t a, uint32_t r) {
    uint32_t o;
    asm("mapa.shared::cluster.u32 %0, %1, %2;" : "=r"(o) : "r"(a), "r"(r));
    return o;
}
__device__ __forceinline__ uint32_t ctarank() {
    uint32_t r; asm("mov.u32 %0, %%cluster_ctarank;" : "=r"(r)); return r;
}
__device__ __forceinline__ void st_async64(uint32_t raddr, u64 v, uint32_t rmbar) {
    asm volatile(
        "st.async.shared::cluster.mbarrier::complete_tx::bytes.b64 [%0], %1, [%2];"
        :: "r"(raddr), "l"(v), "r"(rmbar) : "memory");
}
__device__ __forceinline__ void mbar_init(uint32_t a, uint32_t cnt) {
    asm volatile("mbarrier.init.shared.b64 [%0], %1;" :: "r"(a), "r"(cnt) : "memory");
}
__device__ __forceinline__ void mbar_arrive_expect_tx(uint32_t a, uint32_t bytes) {
    asm volatile("mbarrier.arrive.expect_tx.shared.b64 _, [%0], %1;"
                 :: "r"(a), "r"(bytes) : "memory");
}
__device__ __forceinline__ void mbar_wait(uint32_t a, uint32_t parity) {
    uint32_t done;
    asm volatile(
        "{\n\t.reg .pred p;\n\t"
        "mbarrier.try_wait.parity.acquire.cta.shared::cta.b64 p, [%1], %2;\n\t"
        "selp.b32 %0, 1, 0, p;\n\t}"
        : "=r"(done) : "r"(a), "r"(parity) : "memory");
    if (!done) {
        asm volatile(
            "{\n\t.reg .pred P1;\n\t"
            "WL_%=:\n\t"
            "mbarrier.try_wait.parity.acquire.cta.shared::cta.b64 P1, [%0], %1, 0x989680;\n\t"
            "@P1 bra.uni WD_%=;\n\t"
            "bra.uni WL_%=;\n\t"
            "WD_%=:\n\t}"
            :: "r"(a), "r"(parity) : "memory");
    }
}
#define CLUSTER_SYNC() do { \
    asm volatile("barrier.cluster.arrive.aligned;" ::: "memory"); \
    asm volatile("barrier.cluster.wait.aligned;" ::: "memory");   \
} while (0)

// ---------------- prep: transpose w_hh into [k][g] ----------
__global__ void prep_transpose(const float* __restrict__ wf,
                               const float* __restrict__ wb) {
    int i = blockIdx.x * blockDim.x + threadIdx.x;
    if (i < G3 * H) {
        int g = i / H, k = i - g * H;
        g_wt[k * G3 + g]          = wf[i];
        g_wt[H * G3 + k * G3 + g] = wb[i];
    }
}

// ---------------- gi = emb[text] @ w_ih^T + b_ih  (128x128 FFMA2 tiles) ----
__global__ void __launch_bounds__(256)
gi_gemm2(const int*   __restrict__ text,
         const float* __restrict__ emb,
         const float* __restrict__ wih_f,
         const float* __restrict__ bih_f,
         const float* __restrict__ wih_b,
         const float* __restrict__ bih_b) {
    const int d = blockIdx.z;
    const float* __restrict__ wih = d ? wih_b : wih_f;
    const float* __restrict__ bih = d ? bih_b : bih_f;

    __shared__ float As[KT][PADW];   // [k][m]
    __shared__ float Bs[KT][PADW];   // [k][n]
    __shared__ int   tok[128];

    const int tid = threadIdx.x;
    const int by  = blockIdx.y;
    const int n0  = blockIdx.x * 128;

    if (tid < 128) tok[tid] = text[by * 128 + tid];
    __syncthreads();

    const int kq = tid & 3;
    const int m0 = tid >> 2;
    const int m1 = m0 + 64;
    const long ar0 = (long)tok[m0] * E;
    const long ar1 = (long)tok[m1] * E;
    const int  g0  = n0 + m0, g1 = n0 + m1;
    const bool vg0 = g0 < G3, vg1 = g1 < G3;

    const int ty = tid >> 4, tx = tid & 15;

    u64 acc[8][4];
    #pragma unroll
    for (int i = 0; i < 8; ++i)
        #pragma unroll
        for (int j = 0; j < 4; ++j) acc[i][j] = 0ULL;

    const float4 z4 = make_float4(0.f, 0.f, 0.f, 0.f);
    float4 aV0, aV1, bV0, bV1;

    {
        const int kk = kq * 4;
        aV0 = *(const float4*)&emb[ar0 + kk];
        aV1 = *(const float4*)&emb[ar1 + kk];
        bV0 = vg0 ? *(const float4*)&wih[(size_t)g0 * E + kk] : z4;
        bV1 = vg1 ? *(const float4*)&wih[(size_t)g1 * E + kk] : z4;
    }

    const int NT = (E + KT - 1) / KT;    // 19
    for (int t = 0; t < NT; ++t) {
        __syncthreads();
        As[kq*4+0][m0] = aV0.x; As[kq*4+1][m0] = aV0.y;
        As[kq*4+2][m0] = aV0.z; As[kq*4+3][m0] = aV0.w;
        As[kq*4+0][m1] = aV1.x; As[kq*4+1][m1] = aV1.y;
        As[kq*4+2][m1] = aV1.z; As[kq*4+3][m1] = aV1.w;
        Bs[kq*4+0][m0] = bV0.x; Bs[kq*4+1][m0] = bV0.y;
        Bs[kq*4+2][m0] = bV0.z; Bs[kq*4+3][m0] = bV0.w;
        Bs[kq*4+0][m1] = bV1.x; Bs[kq*4+1][m1] = bV1.y;
        Bs[kq*4+2][m1] = bV1.z; Bs[kq*4+3][m1] = bV1.w;
        __syncthreads();

        if (t + 1 < NT) {
            const int kk = (t + 1) * KT + kq * 4;
            const bool vk = kk < E;
            aV0 = vk ? *(const float4*)&emb[ar0 + kk] : z4;
            aV1 = vk ? *(const float4*)&emb[ar1 + kk] : z4;
            bV0 = (vk && vg0) ? *(const float4*)&wih[(size_t)g0 * E + kk] : z4;
            bV1 = (vk && vg1) ? *(const float4*)&wih[(size_t)g1 * E + kk] : z4;
        }

        #pragma unroll
        for (int k = 0; k < KT; ++k) {
            float4 a0 = *(const float4*)&As[k][ty * 8];
            float4 a1 = *(const float4*)&As[k][ty * 8 + 4];
            float4 b0 = *(const float4*)&Bs[k][tx * 8];
            float4 b1 = *(const float4*)&Bs[k][tx * 8 + 4];
            u64 bp[4] = { pack2(b0.x, b0.y), pack2(b0.z, b0.w),
                          pack2(b1.x, b1.y), pack2(b1.z, b1.w) };
            float av[8] = { a0.x, a0.y, a0.z, a0.w, a1.x, a1.y, a1.z, a1.w };
            #pragma unroll
            for (int i = 0; i < 8; ++i) {
                u64 ap = pack2(av[i], av[i]);
                #pragma unroll
                for (int j = 0; j < 4; ++j) ffma2(acc[i][j], ap, bp[j]);
            }
        }
    }

    float* gout = g_gi + (size_t)d * ROWS * G3;
    #pragma unroll
    for (int i = 0; i < 8; ++i) {
        const int row = by * 128 + ty * 8 + i;
        float o[8];
        #pragma unroll
        for (int j = 0; j < 4; ++j) unpack2(acc[i][j], o[2*j], o[2*j+1]);
        #pragma unroll
        for (int j = 0; j < 8; ++j) {
            const int g = n0 + tx * 8 + j;
            if (g < G3)
                gout[(size_t)row * G3 + g] = o[j] + bih[g];
        }
    }
}

// ---------------- GRU recurrence: 3-CTA cluster, fully parallel phases ------
// rank r owns gate slice g in [r*200, r*200+200).
// Step: mv(b0);mv(b1) -> bar -> {reduce+push b0 | b1 in parallel thread
// groups} -> {wait+gates b0 (thr 0-199) | wait+gates b1 (thr 256-455)} -> bar.
// Matvec tiling: 500 thr = 10 k-chunks(20) x 50 g-quads; LDS.128 h loads.
#define MAILW 608                 // floats per (buf,batch) mail slab
#define TXB   (G3 * 4)            // 2400 B per batch per step
__global__ void __launch_bounds__(512, 1) __cluster_dims__(3, 1, 1)
gru_rec7(const float* __restrict__ bhh_f, const float* __restrict__ bhh_b,
         const float* __restrict__ h0_f,  const float* __restrict__ h0_b) {
    __shared__ __align__(16) u64 hsd0[H];   // (h,h) per k, batch 0
    __shared__ __align__(16) u64 hsd1[H];   // batch 1
    __shared__ u64  redA[1000];             // [kc][g-pair] partials, batch 0
    __shared__ u64  redB[1000];             // batch 1
    __shared__ float mailf[4 * MAILW];      // [buf*2+batch][g]
    __shared__ u64  bo2[100];               // b_hh g-pairs
    __shared__ __align__(8) u64 mbar[4];    // [buf*2+batch]

    const int tid = threadIdx.x;
    const uint32_t rank = ctarank();
    const int group = blockIdx.x / 3;
    const int d  = group >> 4;
    const int b0 = (group & 15) * 2, b1 = b0 + 1;

    const float* bhh = d ? bhh_b : bhh_f;
    const float* h0  = d ? h0_b  : h0_f;

    // ---- weights into registers: 20 k x 4 g per thread, (g0,g1)(g2,g3) ----
    const float* wgd = g_wt + (size_t)d * (H * G3);
    const int kc = tid / 50;       // k-chunk of 20 (0..9)
    const int gq = tid % 50;       // g-quad
    const bool mv = tid < 500;
    u64 wreg[40];
    if (mv) {
        #pragma unroll
        for (int kk = 0; kk < 20; ++kk) {
            const float* wp = wgd + (size_t)(kc * 20 + kk) * G3 + rank * GS + gq * 4;
            wreg[2 * kk + 0] = *(const u64*)(wp);
            wreg[2 * kk + 1] = *(const u64*)(wp + 2);
        }
    }
    if (tid < 100)
        bo2[tid] = *(const u64*)(bhh + rank * GS + tid * 2);
    if (tid < H) {
        float a = (h0[b0 * H + tid] - 0.5f) * (1.0f / H);
        float c = (h0[b1 * H + tid] - 0.5f) * (1.0f / H);
        hsd0[tid] = pack2(a, a);
        hsd1[tid] = pack2(c, c);
    }
    const uint32_t mbar_u = s2u(mbar);
    if (tid == 0) {
        #pragma unroll
        for (int i = 0; i < 4; ++i) {
            mbar_init(mbar_u + i * 8, 1);
            mbar_arrive_expect_tx(mbar_u + i * 8, TXB);   // arm t=0 and t=1
        }
    }
    __syncthreads();
    CLUSTER_SYNC();        // peers' mbarriers armed before any st.async

    const size_t gbase0 = ((size_t)d * ROWS + (size_t)b0 * S) * G3;
    const size_t gbase1 = ((size_t)d * ROWS + (size_t)b1 * S) * G3;
    float* hid0 = g_hid + ((size_t)d * ROWS + (size_t)b0 * S) * H;
    float* hid1 = g_hid + ((size_t)d * ROWS + (size_t)b1 * S) * H;

    const uint32_t mail_u = s2u(mailf);
    const uint32_t mailR[3] = { mapa_u32(mail_u, 0), mapa_u32(mail_u, 1),
                                mapa_u32(mail_u, 2) };
    const uint32_t mbarR[3] = { mapa_u32(mbar_u, 0), mapa_u32(mbar_u, 1),
                                mapa_u32(mbar_u, 2) };

    // gate-group membership
    const bool gA = tid < 200;                    // gates b0, j = tid
    const bool gB = (tid >= 256) && (tid < 456);  // gates b1, j = tid-256
    const int  gj = gA ? tid : (tid - 256);

    for (int t = 0; t < S; ++t) {
        const int s   = d ? (S - 1 - t) : t;
        const int buf = t & 1;
        const uint32_t par = (t >> 1) & 1;

        // gi prefetch (each gate group loads its own batch)
        float gir_ = 0.f, giz_ = 0.f, gin_ = 0.f;
        if (gA | gB) {
            const float* p = g_gi + (gA ? gbase0 : gbase1) + (size_t)s * G3 + gj;
            gir_ = p[0]; giz_ = p[H]; gin_ = p[2 * H];
        }

        // ---- matvecs, both batches, no intervening barrier ----
        if (mv) {
            u64 a0 = 0, a1 = 0, c0 = 0, c1 = 0;
            const ulonglong2* hp0 = (const ulonglong2*)(hsd0 + kc * 20);
            const ulonglong2* hp1 = (const ulonglong2*)(hsd1 + kc * 20);
            #pragma unroll
            for (int kk = 0; kk < 10; ++kk) {
                ulonglong2 h2 = hp0[kk];
                ffma2(a0, wreg[4 * kk + 0], h2.x);
                ffma2(a1, wreg[4 * kk + 1], h2.x);
                ffma2(a0, wreg[4 * kk + 2], h2.y);
                ffma2(a1, wreg[4 * kk + 3], h2.y);
            }
            #pragma unroll
            for (int kk = 0; kk < 10; ++kk) {
                ulonglong2 h2 = hp1[kk];
                ffma2(c0, wreg[4 * kk + 0], h2.x);
                ffma2(c1, wreg[4 * kk + 1], h2.x);
                ffma2(c0, wreg[4 * kk + 2], h2.y);
                ffma2(c1, wreg[4 * kk + 3], h2.y);
            }
            redA[kc * 100 + gq * 2 + 0] = a0;
            redA[kc * 100 + gq * 2 + 1] = a1;
            redB[kc * 100 + gq * 2 + 0] = c0;
            redB[kc * 100 + gq * 2 + 1] = c1;
        }
        __syncthreads();                            // partials ready

        // ---- parallel reduce + push (b0: thr 0-99, b1: thr 128-227) ----
        if (tid < 100) {
            u64 sA = redA[tid];
            #pragma unroll
            for (int q = 1; q < 10; ++q) add2(sA, redA[q * 100 + tid]);
            add2(sA, bo2[tid]);
            const uint32_t off = (uint32_t)((buf * 2 + 0) * MAILW
                                            + rank * GS + tid * 2) * 4u;
            const uint32_t mboff = (uint32_t)(buf * 2 + 0) * 8u;
            #pragma unroll
            for (int rr = 0; rr < 3; ++rr)
                st_async64(mailR[rr] + off, sA, mbarR[rr] + mboff);
        } else if (tid >= 128 && tid < 228) {
            const int p = tid - 128;
            u64 sB = redB[p];
            #pragma unroll
            for (int q = 1; q < 10; ++q) add2(sB, redB[q * 100 + p]);
            add2(sB, bo2[p]);
            const uint32_t off = (uint32_t)((buf * 2 + 1) * MAILW
                                            + rank * GS + p * 2) * 4u;
            const uint32_t mboff = (uint32_t)(buf * 2 + 1) * 8u;
            #pragma unroll
            for (int rr = 0; rr < 3; ++rr)
                st_async64(mailR[rr] + off, sB, mbarR[rr] + mboff);
        }

        // ---- parallel wait + gates ----
        if (gA | gB) {
            const int bslot = gA ? (buf * 2 + 0) : (buf * 2 + 1);
            mbar_wait(mbar_u + bslot * 8, par);
            if ((tid == 0 || tid == 256) && t + 2 < S)
                mbar_arrive_expect_tx(mbar_u + bslot * 8, TXB);
            const float* mb_ = mailf + bslot * MAILW;
            const float hr = mb_[gj], hz = mb_[H + gj], hn = mb_[2 * H + gj];
            u64* hsd = gA ? hsd0 : hsd1;
            float ho, dum; unpack2(hsd[gj], ho, dum);
            const float r = 1.f / (1.f + __expf(-(gir_ + hr)));
            const float z = 1.f / (1.f + __expf(-(giz_ + hz)));
            float xt = gin_ + r * hn;
            xt = fminf(fmaxf(xt, -30.f), 30.f);
            const float e = __expf(-2.f * xt);
            const float n = (1.f - e) / (1.f + e);
            const float hv = (1.f - z) * n + z * ho;
            hsd[gj] = pack2(hv, hv);
            if (rank == 0)
                (gA ? hid0 : hid1)[(size_t)s * H + gj] = hv;
        }
        __syncthreads();                            // hsd stable for next mv
    }
}

// ---------------- final linear: warp per (b,s) row ----------
__global__ void preds_kernel(const float* __restrict__ lin_w,
                             const float* __restrict__ lin_b,
                             float* __restrict__ out) {
    __shared__ float lw[LBL * 2 * H];
    __shared__ float lb[LBL];
    const int tid = threadIdx.x;
    for (int i = tid; i < LBL * 2 * H; i += 256) lw[i] = lin_w[i];
    if (tid < LBL) lb[tid] = lin_b[tid];
    __syncthreads();

    const int wid = tid >> 5, lane = tid & 31;
    const int row = blockIdx.x * 8 + wid;
    const float* hf = g_hid + (size_t)row * H;
    const float* hb = g_hid + (size_t)(ROWS + row) * H;

    float acc[LBL] = {};
    for (int k = lane; k < 2 * H; k += 32) {
        float x = (k < H) ? hf[k] : hb[k - H];
        #pragma unroll
        for (int l = 0; l < LBL; ++l) acc[l] += x * lw[l * 2 * H + k];
    }
    #pragma unroll
    for (int l = 0; l < LBL; ++l) {
        float v = acc[l];
        #pragma unroll
        for (int o = 16; o > 0; o >>= 1) v += __shfl_xor_sync(0xffffffffu, v, o);
        if (lane == 0) out[(size_t)row * LBL + l] = v + lb[l];
    }
}

// ---------------- launch ----------
extern "C" void kernel_launch(void* const* d_in, const int* in_sizes, int n_in,
                              void* d_out, int out_size) {
    const int*   text  = (const int*)  d_in[0];
    const float* emb   = (const float*)d_in[1];
    const float* wih_f = (const float*)d_in[2];
    const float* whh_f = (const float*)d_in[3];
    const float* bih_f = (const float*)d_in[4];
    const float* bhh_f = (const float*)d_in[5];
    const float* wih_b = (const float*)d_in[6];
    const float* whh_b = (const float*)d_in[7];
    const float* bih_b = (const float*)d_in[8];
    const float* bhh_b = (const float*)d_in[9];
    const float* lin_w = (const float*)d_in[10];
    const float* lin_b = (const float*)d_in[11];
    const float* h0_f  = (const float*)d_in[12];
    const float* h0_b  = (const float*)d_in[13];
    float* out = (float*)d_out;

    prep_transpose<<<(G3 * H + 255) / 256, 256>>>(whh_f, whh_b);

    dim3 gg((G3 + 127) / 128, ROWS / 128, 2);   // (5, 128, 2)
    gi_gemm2<<<gg, 256>>>(text, emb, wih_f, bih_f, wih_b, bih_b);

    gru_rec7<<<96, 512>>>(bhh_f, bhh_b, h0_f, h0_b);

    preds_kernel<<<ROWS / 8, 256>>>(lin_w, lin_b, out);
}